// round 10
// baseline (speedup 1.0000x reference)
#include <cuda_runtime.h>
#include <math.h>

#define BB 256
#define TT 512
#define DD 200
#define HH 128
#define FF 128
#define MROWS (BB*TT)
#define LAMBDA 0.5f

// ---- device scratch (static; allocation-free per harness rules) ----
__device__ float g_gamma[MROWS*FF];
__device__ float g_cat  [MROWS*2*FF];
__device__ float g_rlh1 [MROWS*FF];
__device__ float g_beta [MROWS*FF];
__device__ float g_corr [MROWS*FF];
__device__ float g_rl   [MROWS*FF];
__device__ float g_q    [MROWS*FF];
__device__ float g_k    [MROWS*FF];
__device__ float g_v    [MROWS*FF];
__device__ float g_av   [MROWS*FF];
__device__ float g_A0   [(size_t)MROWS*512];
__device__ float g_A1   [(size_t)MROWS*512];
__device__ float g_A2   [(size_t)MROWS*512];
__device__ float g_Bp0  [328*512];
__device__ float g_Bp1  [128*512];
__device__ float g_Bp2  [128*512];
__device__ float g_h    [3*2*HH*BB];     // [layer][parity][h][b]
__device__ unsigned g_bar_cnt;
__device__ unsigned g_bar_gen;

// Pack GEMM-ready B matrices: x-rows of base_w0 + gamma-gate weights (-LAM folded into f gate)
__global__ void pack_kernel(const float* __restrict__ w0,
                            const float* __restrict__ gw0,
                            const float* __restrict__ gw12) {
    int idx = blockIdx.x * blockDim.x + threadIdx.x;
    const int N0 = 328*512;
    if (idx < N0) {
        int k = idx >> 9, n = idx & 511;
        float v;
        if (k < DD) v = w0[(HH + k)*512 + n];
        else {
            int f = k - DD, g = n >> 7, h = n & 127;
            v = gw0[g*16384 + f*128 + h] * (g == 1 ? -LAMBDA : 1.0f);
        }
        g_Bp0[idx] = v;
    } else if (idx < N0 + 65536) {
        int j = idx - N0, f = j >> 9, n = j & 511, g = n >> 7, h = n & 127;
        g_Bp1[j] = gw12[g*16384 + f*128 + h] * (g == 1 ? -LAMBDA : 1.0f);
    } else if (idx < N0 + 2*65536) {
        int j = idx - N0 - 65536, f = j >> 9, n = j & 511, g = n >> 7, h = n & 127;
        g_Bp2[j] = gw12[65536 + g*16384 + f*128 + h] * (g == 1 ? -LAMBDA : 1.0f);
    }
}

// amp/ph embeddings (cat = [ph, amp]) + rlos hidden1
__global__ void ew1_kernel(const float* __restrict__ ampc, const float* __restrict__ phc,
                           const float* __restrict__ rd,
                           const float* __restrict__ aw, const float* __restrict__ ab,
                           const float* __restrict__ pw, const float* __restrict__ pb,
                           const float* __restrict__ w1, const float* __restrict__ b1) {
    int idx = blockIdx.x * blockDim.x + threadIdx.x;
    if (idx >= MROWS*FF) return;
    int r = idx >> 7, f = idx & 127;
    g_cat[r*256 + f]       = tanhf(phc[r]  * pw[f] + pb[f]);
    g_cat[r*256 + 128 + f] = tanhf(ampc[r] * aw[f] + ab[f]);
    g_rlh1[idx] = tanhf(rd[r*2]*w1[f] + rd[r*2+1]*w1[128+f] + b1[f]);
}

__global__ void ew2_kernel() {   // corr = beta*ph + (1-beta)*amp
    int idx = blockIdx.x * blockDim.x + threadIdx.x;
    if (idx >= MROWS*FF) return;
    int r = idx >> 7, f = idx & 127;
    float b = g_beta[idx];
    g_corr[idx] = b*g_cat[r*256 + f] + (1.0f - b)*g_cat[r*256 + 128 + f];
}

__global__ void ew3_kernel() {   // av = sigmoid(dot(q,k)/sqrt(F)) * v
    int r = blockIdx.x, f = threadIdx.x;
    float p = g_q[r*128 + f] * g_k[r*128 + f];
    #pragma unroll
    for (int off = 16; off; off >>= 1) p += __shfl_xor_sync(0xffffffffu, p, off);
    __shared__ float ws[4];
    if ((f & 31) == 0) ws[f >> 5] = p;
    __syncthreads();
    float dot = ws[0] + ws[1] + ws[2] + ws[3];
    float attn = 1.0f / (1.0f + expf(-dot * 0.08838834764831845f));
    g_av[r*128 + f] = attn * g_v[r*128 + f];
}

// Generic fp32 tiled GEMM: C = act(Avirt[M,K]@B[K,N] + bias)
// amode 0: plain A. amode 1: A=gamma shifted (t==0 -> 0 else row r-1).
// amode 2: k<200 -> |Aux[r,k]| ; else shifted gamma col k-200.
__global__ __launch_bounds__(256) void gemm_kernel(
    const float* __restrict__ A, const float* __restrict__ Bm,
    const float* __restrict__ bias, float* __restrict__ C,
    int M, int N, int K, int act, int amode, const float* __restrict__ Aux)
{
    __shared__ __align__(16) float As[16][64];
    __shared__ __align__(16) float Bs[16][64];
    const int tid = threadIdx.x, tx = tid & 15, ty = tid >> 4;
    const int rowBase = blockIdx.y * 64, colBase = blockIdx.x * 64;
    float acc[4][4] = {};
    const int am = tid >> 2, ak0 = (tid & 3) * 4;
    const int bk = tid >> 4, bn0 = (tid & 15) * 4;
    const int r = rowBase + am, tmod = r & (TT - 1);

    for (int k0 = 0; k0 < K; k0 += 16) {
        #pragma unroll
        for (int i = 0; i < 4; i++) {
            int k = k0 + ak0 + i;
            float v = 0.0f;
            if (k < K) {
                if (amode == 0)      v = A[(size_t)r*K + k];
                else if (amode == 1) v = (tmod == 0) ? 0.0f : A[(size_t)(r-1)*FF + k];
                else {
                    if (k < DD) v = fabsf(Aux[(size_t)r*DD + k]);
                    else        v = (tmod == 0) ? 0.0f : A[(size_t)(r-1)*FF + (k - DD)];
                }
            }
            As[ak0 + i][am] = v;
        }
        #pragma unroll
        for (int i = 0; i < 4; i++) {
            int k = k0 + bk;
            Bs[bk][bn0 + i] = (k < K) ? Bm[(size_t)k*N + colBase + bn0 + i] : 0.0f;
        }
        __syncthreads();
        #pragma unroll
        for (int kk = 0; kk < 16; kk++) {
            float4 a4 = *(const float4*)&As[kk][ty*4];
            float4 b4 = *(const float4*)&Bs[kk][tx*4];
            float av[4] = {a4.x, a4.y, a4.z, a4.w};
            float bv[4] = {b4.x, b4.y, b4.z, b4.w};
            #pragma unroll
            for (int i = 0; i < 4; i++)
                #pragma unroll
                for (int j = 0; j < 4; j++) acc[i][j] += av[i]*bv[j];
        }
        __syncthreads();
    }
    #pragma unroll
    for (int i = 0; i < 4; i++) {
        int row = rowBase + ty*4 + i;
        #pragma unroll
        for (int j = 0; j < 4; j++) {
            int col = colBase + tx*4 + j;
            float v = acc[i][j] + (bias ? bias[col] : 0.0f);
            if (act == 1)      v = tanhf(v);
            else if (act == 2) v = 1.0f / (1.0f + expf(-v));
            C[(size_t)row*N + col] = v;
        }
    }
}

__global__ void bar_init_kernel() { g_bar_cnt = 0u; g_bar_gen = 0u; }

__device__ __forceinline__ void grid_barrier(unsigned* gen) {
    __syncthreads();
    if (threadIdx.x == 0) {
        unsigned target = *gen + 1u;
        __threadfence();
        unsigned old = atomicAdd(&g_bar_cnt, 1u);
        if (old == gridDim.x - 1u) {
            *(volatile unsigned*)&g_bar_cnt = 0u;
            __threadfence();
            atomicExch(&g_bar_gen, target);
        } else {
            while (*(volatile unsigned*)&g_bar_gen < target) { }
        }
        __threadfence();
    }
    __syncthreads();
    *gen += 1u;
}

// Persistent wavefront recurrence: 128 blocks = 8 b-tiles(32) x 16 h-tiles(8)
__global__ __launch_bounds__(256, 1) void lstm_kernel(
    const float* __restrict__ w0g, const float* __restrict__ w12g)
{
    extern __shared__ __align__(16) float sm[];
    float* w0_s = sm;                   // [128][32]
    float* w1_s = w0_s + 128*32;        // [256][32]
    float* w2_s = w1_s + 256*32;        // [256][32]
    float* h_s  = w2_s + 256*32;        // [3][128][32]
    float* z_s  = h_s  + 3*128*32;      // [32][33]

    const int tid = threadIdx.x;
    const int btile = blockIdx.x & 7, htile = blockIdx.x >> 3;
    const int col = tid & 31, bg = tid >> 5;
    const int ncol = (col >> 3)*128 + htile*8 + (col & 7);
    const int ub = tid & 31, uh = tid >> 5;

    for (int idx = tid; idx < 128*32; idx += 256) {
        int k = idx >> 5, c = idx & 31;
        int n = (c >> 3)*128 + htile*8 + (c & 7);
        w0_s[idx] = w0g[k*512 + n];
    }
    for (int idx = tid; idx < 256*32; idx += 256) {
        int k = idx >> 5, c = idx & 31;
        int n = (c >> 3)*128 + htile*8 + (c & 7);
        w1_s[idx] = w12g[k*512 + n];
        w2_s[idx] = w12g[256*512 + k*512 + n];
    }
    {
        int base = blockIdx.x * 1536;
        for (int i = tid; i < 1536; i += 256) g_h[base + i] = 0.0f;
    }

    float cst[3] = {0.0f, 0.0f, 0.0f};
    const float* gA0 = g_A0; const float* gA1 = g_A1; const float* gA2 = g_A2;

    unsigned gen = 0;
    grid_barrier(&gen);

    for (int w = 0; w < TT + 2; w++) {
        const int pp = (w + 1) & 1, cp = w & 1;
        for (int idx = tid; idx < 3*128*32; idx += 256) {
            int l = idx / 4096, rem = idx - l*4096;
            int k = rem >> 5, b = rem & 31;
            h_s[idx] = __ldcg(&g_h[((l*2 + pp)*128 + k)*256 + btile*32 + b]);
        }
        __syncthreads();

        #pragma unroll
        for (int l = 0; l < 3; l++) {
            int s = w - l;
            if (s < 0 || s >= TT) continue;   // uniform across block

            const float* gA = (l == 0) ? gA0 : (l == 1) ? gA1 : gA2;
            const float* Ap = gA + (size_t)((btile*32 + bg*4)*TT + s)*512 + ncol;
            float a0 = Ap[0];
            float a1 = Ap[(size_t)TT*512];
            float a2 = Ap[(size_t)2*TT*512];
            float a3 = Ap[(size_t)3*TT*512];

            if (l == 0) {
                #pragma unroll 4
                for (int k = 0; k < 128; k++) {
                    float wv = w0_s[k*32 + col];
                    float4 h4 = *(const float4*)&h_s[k*32 + bg*4];
                    a0 += h4.x*wv; a1 += h4.y*wv; a2 += h4.z*wv; a3 += h4.w*wv;
                }
            } else {
                const float* wl   = (l == 1) ? w1_s : w2_s;
                const float* hown = h_s + l*4096;
                const float* hlow = h_s + (l-1)*4096;
                #pragma unroll 4
                for (int k = 0; k < 128; k++) {
                    float wv = wl[k*32 + col];
                    float4 h4 = *(const float4*)&hown[k*32 + bg*4];
                    a0 += h4.x*wv; a1 += h4.y*wv; a2 += h4.z*wv; a3 += h4.w*wv;
                }
                #pragma unroll 4
                for (int k = 0; k < 128; k++) {
                    float wv = wl[(128 + k)*32 + col];
                    float4 h4 = *(const float4*)&hlow[k*32 + bg*4];
                    a0 += h4.x*wv; a1 += h4.y*wv; a2 += h4.z*wv; a3 += h4.w*wv;
                }
            }
            z_s[col*33 + bg*4 + 0] = a0;
            z_s[col*33 + bg*4 + 1] = a1;
            z_s[col*33 + bg*4 + 2] = a2;
            z_s[col*33 + bg*4 + 3] = a3;
            __syncthreads();

            {
                float zi = z_s[(0*8 + uh)*33 + ub];
                float zf = z_s[(1*8 + uh)*33 + ub];
                float zc = z_s[(2*8 + uh)*33 + ub];
                float zo = z_s[(3*8 + uh)*33 + ub];
                float iv = 1.0f / (1.0f + expf(-zi));
                float fv = 1.0f / (1.0f + expf(-zf));
                float cv = tanhf(zc);
                float ov = 1.0f / (1.0f + expf(-zo));
                cst[l] = fv*cst[l] + iv*cv;
                float hn = ov * tanhf(cst[l]);
                g_h[((l*2 + cp)*128 + htile*8 + uh)*256 + btile*32 + ub] = hn;
            }
            __syncthreads();
        }
        grid_barrier(&gen);
    }
}

__global__ void out_kernel(const float* __restrict__ rw, const float* __restrict__ rb,
                           float* __restrict__ out) {
    int b = threadIdx.x;
    const int p = (TT + 1) & 1;
    float a0 = rb[0], a1 = rb[1];
    #pragma unroll 4
    for (int h = 0; h < HH; h++) {
        float hv = g_h[((2*2 + p)*128 + h)*256 + b];
        a0 += hv * rw[h*2 + 0];
        a1 += hv * rw[h*2 + 1];
    }
    out[b*2 + 0] = a0;
    out[b*2 + 1] = a1;
}

extern "C" void kernel_launch(void* const* d_in, const int* in_sizes, int n_in,
                              void* d_out, int out_size) {
    (void)in_sizes; (void)n_in; (void)out_size;
    const float* hrrp     = (const float*)d_in[0];
    const float* ampc     = (const float*)d_in[1];
    const float* phc      = (const float*)d_in[2];
    const float* rd       = (const float*)d_in[3];
    const float* f_amp_w  = (const float*)d_in[4];
    const float* f_amp_b  = (const float*)d_in[5];
    const float* f_ph_w   = (const float*)d_in[6];
    const float* f_ph_b   = (const float*)d_in[7];
    const float* f_gate_w = (const float*)d_in[8];
    const float* f_gate_b = (const float*)d_in[9];
    const float* f_rl_w1  = (const float*)d_in[10];
    const float* f_rl_b1  = (const float*)d_in[11];
    const float* f_rl_w2  = (const float*)d_in[12];
    const float* f_rl_b2  = (const float*)d_in[13];
    const float* f_q_w    = (const float*)d_in[14];
    const float* f_q_b    = (const float*)d_in[15];
    const float* f_k_w    = (const float*)d_in[16];
    const float* f_k_b    = (const float*)d_in[17];
    const float* f_v_w    = (const float*)d_in[18];
    const float* f_v_b    = (const float*)d_in[19];
    const float* f_out_w  = (const float*)d_in[20];
    const float* f_out_b  = (const float*)d_in[21];
    const float* base_w0  = (const float*)d_in[22];
    const float* base_b0  = (const float*)d_in[23];
    const float* gam_w0   = (const float*)d_in[24];
    const float* base_w12 = (const float*)d_in[25];
    const float* base_b12 = (const float*)d_in[26];
    const float* gam_w12  = (const float*)d_in[27];
    const float* reg_w    = (const float*)d_in[28];
    const float* reg_b    = (const float*)d_in[29];
    float* out = (float*)d_out;

    float *p_cat, *p_beta, *p_rlh1, *p_corr, *p_rl, *p_q, *p_k, *p_v, *p_av, *p_gamma;
    float *p_A0, *p_A1, *p_A2, *p_Bp0, *p_Bp1, *p_Bp2;
    cudaGetSymbolAddress((void**)&p_cat,   g_cat);
    cudaGetSymbolAddress((void**)&p_beta,  g_beta);
    cudaGetSymbolAddress((void**)&p_rlh1,  g_rlh1);
    cudaGetSymbolAddress((void**)&p_corr,  g_corr);
    cudaGetSymbolAddress((void**)&p_rl,    g_rl);
    cudaGetSymbolAddress((void**)&p_q,     g_q);
    cudaGetSymbolAddress((void**)&p_k,     g_k);
    cudaGetSymbolAddress((void**)&p_v,     g_v);
    cudaGetSymbolAddress((void**)&p_av,    g_av);
    cudaGetSymbolAddress((void**)&p_gamma, g_gamma);
    cudaGetSymbolAddress((void**)&p_A0,    g_A0);
    cudaGetSymbolAddress((void**)&p_A1,    g_A1);
    cudaGetSymbolAddress((void**)&p_A2,    g_A2);
    cudaGetSymbolAddress((void**)&p_Bp0,   g_Bp0);
    cudaGetSymbolAddress((void**)&p_Bp1,   g_Bp1);
    cudaGetSymbolAddress((void**)&p_Bp2,   g_Bp2);

    pack_kernel<<<1168, 256>>>(base_w0, gam_w0, gam_w12);
    ew1_kernel<<<65536, 256>>>(ampc, phc, rd, f_amp_w, f_amp_b, f_ph_w, f_ph_b, f_rl_w1, f_rl_b1);

    dim3 gF(2, 2048), gA(8, 2048);
    gemm_kernel<<<gF, 256>>>(p_cat,  f_gate_w, f_gate_b, p_beta, MROWS, 128, 256, 2, 0, nullptr);
    ew2_kernel<<<65536, 256>>>();
    gemm_kernel<<<gF, 256>>>(p_rlh1, f_rl_w2,  f_rl_b2,  p_rl,   MROWS, 128, 128, 1, 0, nullptr);
    gemm_kernel<<<gF, 256>>>(p_corr, f_q_w,    f_q_b,    p_q,    MROWS, 128, 128, 0, 0, nullptr);
    gemm_kernel<<<gF, 256>>>(p_rl,   f_k_w,    f_k_b,    p_k,    MROWS, 128, 128, 0, 0, nullptr);
    gemm_kernel<<<gF, 256>>>(p_rl,   f_v_w,    f_v_b,    p_v,    MROWS, 128, 128, 0, 0, nullptr);
    ew3_kernel<<<MROWS, 128>>>();
    gemm_kernel<<<gF, 256>>>(p_av,   f_out_w,  f_out_b,  p_gamma, MROWS, 128, 128, 0, 0, nullptr);

    gemm_kernel<<<gA, 256>>>(p_gamma, p_Bp0, base_b0,        p_A0, MROWS, 512, 328, 0, 2, hrrp);
    gemm_kernel<<<gA, 256>>>(p_gamma, p_Bp1, base_b12,       p_A1, MROWS, 512, 128, 0, 1, nullptr);
    gemm_kernel<<<gA, 256>>>(p_gamma, p_Bp2, base_b12 + 512, p_A2, MROWS, 512, 128, 0, 1, nullptr);

    bar_init_kernel<<<1, 1>>>();
    const int SMEM_BYTES = (128*32 + 256*32 + 256*32 + 3*128*32 + 32*33) * 4;  // 135296
    cudaFuncSetAttribute(lstm_kernel, cudaFuncAttributeMaxDynamicSharedMemorySize, SMEM_BYTES);
    lstm_kernel<<<128, 256, SMEM_BYTES>>>(base_w0, base_w12);
    out_kernel<<<1, 256>>>(reg_w, reg_b, out);
}

// round 13
// speedup vs baseline: 1.1451x; 1.1451x over previous
#include <cuda_runtime.h>
#include <math.h>

#define BB 256
#define TT 512
#define DD 200
#define HH 128
#define FF 128
#define MROWS (BB*TT)
#define LAMBDA 0.5f

typedef unsigned long long ull;

__device__ __forceinline__ ull f2dup(float x) {
    ull r; asm("mov.b64 %0,{%1,%1};" : "=l"(r) : "f"(x)); return r;
}
__device__ __forceinline__ ull f2pack(float x, float y) {
    ull r; asm("mov.b64 %0,{%1,%2};" : "=l"(r) : "f"(x), "f"(y)); return r;
}
__device__ __forceinline__ ull ffma2(ull a, ull b, ull c) {
    ull d; asm("fma.rn.f32x2 %0,%1,%2,%3;" : "=l"(d) : "l"(a), "l"(b), "l"(c)); return d;
}
__device__ __forceinline__ float2 f2unpack(ull v) {
    float2 r; asm("mov.b64 {%0,%1},%2;" : "=f"(r.x), "=f"(r.y) : "l"(v)); return r;
}

// ---- device scratch ----
__device__ float g_gamma[MROWS*FF];
__device__ float g_cat  [MROWS*2*FF];
__device__ float g_rlh1 [MROWS*FF];
__device__ float g_corr [MROWS*FF];
__device__ float g_rl   [MROWS*FF];
__device__ float g_q    [MROWS*FF];
__device__ float g_k    [MROWS*FF];
__device__ float g_v    [MROWS*FF];
__device__ float g_av   [MROWS*FF];
__device__ float g_A0   [(size_t)MROWS*512];
__device__ float g_A1   [(size_t)MROWS*512];
__device__ float g_A2   [(size_t)MROWS*512];
__device__ float g_Bp0  [328*512];
__device__ float g_Bp1  [128*512];
__device__ float g_Bp2  [128*512];
__device__ float g_h    [3*2*HH*BB];     // [layer][parity][h][b]
__device__ unsigned g_bar_cnt;
__device__ unsigned g_bar_gen;

// Pack GEMM-ready B matrices (-LAMBDA folded into f gate)
__global__ void pack_kernel(const float* __restrict__ w0,
                            const float* __restrict__ gw0,
                            const float* __restrict__ gw12) {
    int idx = blockIdx.x * blockDim.x + threadIdx.x;
    const int N0 = 328*512;
    if (idx < N0) {
        int k = idx >> 9, n = idx & 511;
        float v;
        if (k < DD) v = w0[(HH + k)*512 + n];
        else {
            int f = k - DD, g = n >> 7, h = n & 127;
            v = gw0[g*16384 + f*128 + h] * (g == 1 ? -LAMBDA : 1.0f);
        }
        g_Bp0[idx] = v;
    } else if (idx < N0 + 65536) {
        int j = idx - N0, f = j >> 9, n = j & 511, g = n >> 7, h = n & 127;
        g_Bp1[j] = gw12[g*16384 + f*128 + h] * (g == 1 ? -LAMBDA : 1.0f);
    } else if (idx < N0 + 2*65536) {
        int j = idx - N0 - 65536, f = j >> 9, n = j & 511, g = n >> 7, h = n & 127;
        g_Bp2[j] = gw12[65536 + g*16384 + f*128 + h] * (g == 1 ? -LAMBDA : 1.0f);
    }
}

// amp/ph embeddings (cat = [ph, amp]) + rlos hidden1
__global__ void ew1_kernel(const float* __restrict__ ampc, const float* __restrict__ phc,
                           const float* __restrict__ rd,
                           const float* __restrict__ aw, const float* __restrict__ ab,
                           const float* __restrict__ pw, const float* __restrict__ pb,
                           const float* __restrict__ w1, const float* __restrict__ b1) {
    int idx = blockIdx.x * blockDim.x + threadIdx.x;
    if (idx >= MROWS*FF) return;
    int r = idx >> 7, f = idx & 127;
    g_cat[r*256 + f]       = tanhf(phc[r]  * pw[f] + pb[f]);
    g_cat[r*256 + 128 + f] = tanhf(ampc[r] * aw[f] + ab[f]);
    g_rlh1[idx] = tanhf(rd[r*2]*w1[f] + rd[r*2+1]*w1[128+f] + b1[f]);
}

__global__ void ew3_kernel() {   // av = sigmoid(dot(q,k)/sqrt(F)) * v
    int r = blockIdx.x, f = threadIdx.x;
    float p = g_q[r*128 + f] * g_k[r*128 + f];
    #pragma unroll
    for (int off = 16; off; off >>= 1) p += __shfl_xor_sync(0xffffffffu, p, off);
    __shared__ float ws[4];
    if ((f & 31) == 0) ws[f >> 5] = p;
    __syncthreads();
    float dot = ws[0] + ws[1] + ws[2] + ws[3];
    float attn = 1.0f / (1.0f + expf(-dot * 0.08838834764831845f));
    g_av[r*128 + f] = attn * g_v[r*128 + f];
}

// fp32 GEMM with packed fma.rn.f32x2. Tile 128x128, 8x8 per-thread.
// amode 0: plain A[M,K]. amode 1: A=gamma time-shifted. amode 2: |Aux| || shifted gamma.
// act: 0 none, 1 tanh, 2 sigmoid, 3 sigmoid->corr blend (A must be g_cat, N==128)
__global__ __launch_bounds__(256) void gemm_kernel(
    const float* __restrict__ A, const float* __restrict__ Bm,
    const float* __restrict__ bias, float* __restrict__ C,
    int M, int N, int K, int act, int amode, const float* __restrict__ Aux)
{
    __shared__ __align__(16) float As[16][128];
    __shared__ __align__(16) float Bs[16][128];
    const int tid = threadIdx.x;
    const int tx = tid & 15, ty = tid >> 4;
    const int rowBase = blockIdx.y * 128, colBase = blockIdx.x * 128;
    ull acc[8][4] = {};

    const int lm = tid >> 1, lk0 = (tid & 1) * 8;
    const int r = rowBase + lm;
    const int tmod = r & (TT - 1);

    for (int k0 = 0; k0 < K; k0 += 16) {
        #pragma unroll
        for (int i = 0; i < 8; i++) {
            int k = k0 + lk0 + i;
            float v = 0.0f;
            if (k < K) {
                if (amode == 0)      v = A[(size_t)r*K + k];
                else if (amode == 1) v = (tmod == 0) ? 0.0f : A[(size_t)(r-1)*FF + k];
                else {
                    if (k < DD) v = fabsf(Aux[(size_t)r*DD + k]);
                    else        v = (tmod == 0) ? 0.0f : A[(size_t)(r-1)*FF + (k - DD)];
                }
            }
            As[lk0 + i][lm] = v;
        }
        #pragma unroll
        for (int i = 0; i < 2; i++) {
            int f4 = tid + i*256;             // 0..511
            int bk = f4 >> 5, bc = (f4 & 31) * 4;
            float4 v = make_float4(0.f, 0.f, 0.f, 0.f);
            if (k0 + bk < K) v = *(const float4*)&Bm[(size_t)(k0 + bk)*N + colBase + bc];
            *(float4*)&Bs[bk][bc] = v;
        }
        __syncthreads();
        #pragma unroll
        for (int kk = 0; kk < 16; kk++) {
            float4 a0 = *(const float4*)&As[kk][ty*4];
            float4 a1 = *(const float4*)&As[kk][64 + ty*4];
            ulonglong2 b0 = *(const ulonglong2*)&Bs[kk][tx*4];
            ulonglong2 b1 = *(const ulonglong2*)&Bs[kk][64 + tx*4];
            ull ad[8] = {f2dup(a0.x), f2dup(a0.y), f2dup(a0.z), f2dup(a0.w),
                         f2dup(a1.x), f2dup(a1.y), f2dup(a1.z), f2dup(a1.w)};
            ull bd[4] = {b0.x, b0.y, b1.x, b1.y};
            #pragma unroll
            for (int i = 0; i < 8; i++)
                #pragma unroll
                for (int j = 0; j < 4; j++) acc[i][j] = ffma2(ad[i], bd[j], acc[i][j]);
        }
        __syncthreads();
    }

    #pragma unroll
    for (int rh = 0; rh < 2; rh++) {
        #pragma unroll
        for (int i = 0; i < 4; i++) {
            int row = rowBase + rh*64 + ty*4 + i;
            #pragma unroll
            for (int ch = 0; ch < 2; ch++) {
                int col = colBase + ch*64 + tx*4;
                float2 p0 = f2unpack(acc[rh*4 + i][ch*2]);
                float2 p1 = f2unpack(acc[rh*4 + i][ch*2 + 1]);
                float v[4] = {p0.x, p0.y, p1.x, p1.y};
                #pragma unroll
                for (int j = 0; j < 4; j++) {
                    float x = v[j] + (bias ? bias[col + j] : 0.0f);
                    if (act == 1)      x = tanhf(x);
                    else if (act >= 2) x = 1.0f / (1.0f + expf(-x));
                    v[j] = x;
                }
                if (act == 3) {   // beta -> corr blend (A = g_cat, stride 256)
                    #pragma unroll
                    for (int j = 0; j < 4; j++) {
                        float ph = A[(size_t)row*256 + col + j];
                        float am = A[(size_t)row*256 + 128 + col + j];
                        v[j] = v[j]*ph + (1.0f - v[j])*am;
                    }
                }
                *(float4*)&C[(size_t)row*N + col] = make_float4(v[0], v[1], v[2], v[3]);
            }
        }
    }
}

__global__ void bar_init_kernel() { g_bar_cnt = 0u; g_bar_gen = 0u; }

__device__ __forceinline__ void grid_barrier(unsigned* gen) {
    __syncthreads();
    if (threadIdx.x == 0) {
        unsigned target = *gen + 1u;
        __threadfence();
        unsigned old = atomicAdd(&g_bar_cnt, 1u);
        if (old == gridDim.x - 1u) {
            *(volatile unsigned*)&g_bar_cnt = 0u;
            __threadfence();
            atomicExch(&g_bar_gen, target);
        } else {
            while (*(volatile unsigned*)&g_bar_gen < target) { }
        }
        __threadfence();
    }
    __syncthreads();
    *gen += 1u;
}

// Persistent wavefront recurrence: 128 blocks = 8 b-tiles(32) x 16 h-tiles(8)
__global__ __launch_bounds__(256, 1) void lstm_kernel(
    const float* __restrict__ w0g, const float* __restrict__ w12g)
{
    extern __shared__ __align__(16) float sm[];
    float* w0_s = sm;                   // [128][32]
    float* w1_s = w0_s + 128*32;        // [256][32]
    float* w2_s = w1_s + 256*32;        // [256][32]
    float* h_s  = w2_s + 256*32;        // [3][128][32]
    float* z_s  = h_s  + 3*128*32;      // [32][33]

    const int tid = threadIdx.x;
    const int btile = blockIdx.x & 7, htile = blockIdx.x >> 3;
    const int col = tid & 31, bg = tid >> 5;
    const int ncol = (col >> 3)*128 + htile*8 + (col & 7);
    const int ub = tid & 31, uh = tid >> 5;

    for (int idx = tid; idx < 128*32; idx += 256) {
        int k = idx >> 5, c = idx & 31;
        int n = (c >> 3)*128 + htile*8 + (c & 7);
        w0_s[idx] = w0g[k*512 + n];
    }
    for (int idx = tid; idx < 256*32; idx += 256) {
        int k = idx >> 5, c = idx & 31;
        int n = (c >> 3)*128 + htile*8 + (c & 7);
        w1_s[idx] = w12g[k*512 + n];
        w2_s[idx] = w12g[256*512 + k*512 + n];
    }
    {
        int base = blockIdx.x * 1536;
        for (int i = tid; i < 1536; i += 256) g_h[base + i] = 0.0f;
    }

    float cst[3] = {0.0f, 0.0f, 0.0f};
    const float* gA0 = g_A0; const float* gA1 = g_A1; const float* gA2 = g_A2;

    unsigned gen = 0;
    grid_barrier(&gen);

    for (int w = 0; w < TT + 2; w++) {
        const int pp = (w + 1) & 1, cp = w & 1;
        for (int idx = tid; idx < 3*128*32; idx += 256) {
            int l = idx / 4096, rem = idx - l*4096;
            int k = rem >> 5, b = rem & 31;
            h_s[idx] = __ldcg(&g_h[((l*2 + pp)*128 + k)*256 + btile*32 + b]);
        }
        __syncthreads();

        #pragma unroll
        for (int l = 0; l < 3; l++) {
            int s = w - l;
            if (s < 0 || s >= TT) continue;   // uniform across block

            const float* gA = (l == 0) ? gA0 : (l == 1) ? gA1 : gA2;
            const float* Ap = gA + (size_t)((btile*32 + bg*4)*TT + s)*512 + ncol;
            ull p01 = f2pack(Ap[0], Ap[(size_t)TT*512]);
            ull p23 = f2pack(Ap[(size_t)2*TT*512], Ap[(size_t)3*TT*512]);

            if (l == 0) {
                #pragma unroll 4
                for (int k = 0; k < 128; k++) {
                    ull wd = f2dup(w0_s[k*32 + col]);
                    ulonglong2 h2 = *(const ulonglong2*)&h_s[k*32 + bg*4];
                    p01 = ffma2(wd, h2.x, p01);
                    p23 = ffma2(wd, h2.y, p23);
                }
            } else {
                const float* wl   = (l == 1) ? w1_s : w2_s;
                const float* hown = h_s + l*4096;
                const float* hlow = h_s + (l-1)*4096;
                #pragma unroll 4
                for (int k = 0; k < 128; k++) {
                    ull wd = f2dup(wl[k*32 + col]);
                    ulonglong2 h2 = *(const ulonglong2*)&hown[k*32 + bg*4];
                    p01 = ffma2(wd, h2.x, p01);
                    p23 = ffma2(wd, h2.y, p23);
                }
                #pragma unroll 4
                for (int k = 0; k < 128; k++) {
                    ull wd = f2dup(wl[(128 + k)*32 + col]);
                    ulonglong2 h2 = *(const ulonglong2*)&hlow[k*32 + bg*4];
                    p01 = ffma2(wd, h2.x, p01);
                    p23 = ffma2(wd, h2.y, p23);
                }
            }
            float2 u01 = f2unpack(p01), u23 = f2unpack(p23);
            z_s[col*33 + bg*4 + 0] = u01.x;
            z_s[col*33 + bg*4 + 1] = u01.y;
            z_s[col*33 + bg*4 + 2] = u23.x;
            z_s[col*33 + bg*4 + 3] = u23.y;
            __syncthreads();

            {
                float zi = z_s[(0*8 + uh)*33 + ub];
                float zf = z_s[(1*8 + uh)*33 + ub];
                float zc = z_s[(2*8 + uh)*33 + ub];
                float zo = z_s[(3*8 + uh)*33 + ub];
                float iv = 1.0f / (1.0f + expf(-zi));
                float fv = 1.0f / (1.0f + expf(-zf));
                float cv = tanhf(zc);
                float ov = 1.0f / (1.0f + expf(-zo));
                cst[l] = fv*cst[l] + iv*cv;
                float hn = ov * tanhf(cst[l]);
                g_h[((l*2 + cp)*128 + htile*8 + uh)*256 + btile*32 + ub] = hn;
            }
            __syncthreads();
        }
        grid_barrier(&gen);
    }
}

__global__ void out_kernel(const float* __restrict__ rw, const float* __restrict__ rb,
                           float* __restrict__ out) {
    int b = threadIdx.x;
    const int p = (TT + 1) & 1;
    float a0 = rb[0], a1 = rb[1];
    #pragma unroll 4
    for (int h = 0; h < HH; h++) {
        float hv = g_h[((2*2 + p)*128 + h)*256 + b];
        a0 += hv * rw[h*2 + 0];
        a1 += hv * rw[h*2 + 1];
    }
    out[b*2 + 0] = a0;
    out[b*2 + 1] = a1;
}

extern "C" void kernel_launch(void* const* d_in, const int* in_sizes, int n_in,
                              void* d_out, int out_size) {
    (void)in_sizes; (void)n_in; (void)out_size;
    const float* hrrp     = (const float*)d_in[0];
    const float* ampc     = (const float*)d_in[1];
    const float* phc      = (const float*)d_in[2];
    const float* rd       = (const float*)d_in[3];
    const float* f_amp_w  = (const float*)d_in[4];
    const float* f_amp_b  = (const float*)d_in[5];
    const float* f_ph_w   = (const float*)d_in[6];
    const float* f_ph_b   = (const float*)d_in[7];
    const float* f_gate_w = (const float*)d_in[8];
    const float* f_gate_b = (const float*)d_in[9];
    const float* f_rl_w1  = (const float*)d_in[10];
    const float* f_rl_b1  = (const float*)d_in[11];
    const float* f_rl_w2  = (const float*)d_in[12];
    const float* f_rl_b2  = (const float*)d_in[13];
    const float* f_q_w    = (const float*)d_in[14];
    const float* f_q_b    = (const float*)d_in[15];
    const float* f_k_w    = (const float*)d_in[16];
    const float* f_k_b    = (const float*)d_in[17];
    const float* f_v_w    = (const float*)d_in[18];
    const float* f_v_b    = (const float*)d_in[19];
    const float* f_out_w  = (const float*)d_in[20];
    const float* f_out_b  = (const float*)d_in[21];
    const float* base_w0  = (const float*)d_in[22];
    const float* base_b0  = (const float*)d_in[23];
    const float* gam_w0   = (const float*)d_in[24];
    const float* base_w12 = (const float*)d_in[25];
    const float* base_b12 = (const float*)d_in[26];
    const float* gam_w12  = (const float*)d_in[27];
    const float* reg_w    = (const float*)d_in[28];
    const float* reg_b    = (const float*)d_in[29];
    float* out = (float*)d_out;

    float *p_cat, *p_rlh1, *p_corr, *p_rl, *p_q, *p_k, *p_v, *p_av, *p_gamma;
    float *p_A0, *p_A1, *p_A2, *p_Bp0, *p_Bp1, *p_Bp2;
    cudaGetSymbolAddress((void**)&p_cat,   g_cat);
    cudaGetSymbolAddress((void**)&p_rlh1,  g_rlh1);
    cudaGetSymbolAddress((void**)&p_corr,  g_corr);
    cudaGetSymbolAddress((void**)&p_rl,    g_rl);
    cudaGetSymbolAddress((void**)&p_q,     g_q);
    cudaGetSymbolAddress((void**)&p_k,     g_k);
    cudaGetSymbolAddress((void**)&p_v,     g_v);
    cudaGetSymbolAddress((void**)&p_av,    g_av);
    cudaGetSymbolAddress((void**)&p_gamma, g_gamma);
    cudaGetSymbolAddress((void**)&p_A0,    g_A0);
    cudaGetSymbolAddress((void**)&p_A1,    g_A1);
    cudaGetSymbolAddress((void**)&p_A2,    g_A2);
    cudaGetSymbolAddress((void**)&p_Bp0,   g_Bp0);
    cudaGetSymbolAddress((void**)&p_Bp1,   g_Bp1);
    cudaGetSymbolAddress((void**)&p_Bp2,   g_Bp2);

    pack_kernel<<<1168, 256>>>(base_w0, gam_w0, gam_w12);
    ew1_kernel<<<65536, 256>>>(ampc, phc, rd, f_amp_w, f_amp_b, f_ph_w, f_ph_b, f_rl_w1, f_rl_b1);

    dim3 gF(1, 1024), gA(4, 1024);
    // beta GEMM fused with corr blend (act=3): writes corr directly
    gemm_kernel<<<gF, 256>>>(p_cat,  f_gate_w, f_gate_b, p_corr, MROWS, 128, 256, 3, 0, nullptr);
    gemm_kernel<<<gF, 256>>>(p_rlh1, f_rl_w2,  f_rl_b2,  p_rl,   MROWS, 128, 128, 1, 0, nullptr);
    gemm_kernel<<<gF, 256>>>(p_corr, f_q_w,    f_q_b,    p_q,    MROWS, 128, 128, 0, 0, nullptr);
    gemm_kernel<<<gF, 256>>>(p_rl,   f_k_w,    f_k_b,    p_k,    MROWS, 128, 128, 0, 0, nullptr);
    gemm_kernel<<<gF, 256>>>(p_rl,   f_v_w,    f_v_b,    p_v,    MROWS, 128, 128, 0, 0, nullptr);
    ew3_kernel<<<MROWS, 128>>>();
    gemm_kernel<<<gF, 256>>>(p_av,   f_out_w,  f_out_b,  p_gamma, MROWS, 128, 128, 0, 0, nullptr);

    gemm_kernel<<<gA, 256>>>(p_gamma, p_Bp0, base_b0,        p_A0, MROWS, 512, 328, 0, 2, hrrp);
    gemm_kernel<<<gA, 256>>>(p_gamma, p_Bp1, base_b12,       p_A1, MROWS, 512, 128, 0, 1, nullptr);
    gemm_kernel<<<gA, 256>>>(p_gamma, p_Bp2, base_b12 + 512, p_A2, MROWS, 512, 128, 0, 1, nullptr);

    bar_init_kernel<<<1, 1>>>();
    const int SMEM_BYTES = (128*32 + 256*32 + 256*32 + 3*128*32 + 32*33) * 4;  // 135296
    cudaFuncSetAttribute(lstm_kernel, cudaFuncAttributeMaxDynamicSharedMemorySize, SMEM_BYTES);
    lstm_kernel<<<128, 256, SMEM_BYTES>>>(base_w0, base_w12);
    out_kernel<<<1, 256>>>(reg_w, reg_b, out);
}

// round 14
// speedup vs baseline: 1.3840x; 1.2087x over previous
#include <cuda_runtime.h>
#include <math.h>

#define BB 256
#define TT 512
#define DD 200
#define HH 128
#define FF 128
#define MROWS (BB*TT)
#define LAMBDA 0.5f

typedef unsigned long long ull;

__device__ __forceinline__ ull f2dup(float x) {
    ull r; asm("mov.b64 %0,{%1,%1};" : "=l"(r) : "f"(x)); return r;
}
__device__ __forceinline__ ull f2pack(float x, float y) {
    ull r; asm("mov.b64 %0,{%1,%2};" : "=l"(r) : "f"(x), "f"(y)); return r;
}
__device__ __forceinline__ ull ffma2(ull a, ull b, ull c) {
    ull d; asm("fma.rn.f32x2 %0,%1,%2,%3;" : "=l"(d) : "l"(a), "l"(b), "l"(c)); return d;
}
__device__ __forceinline__ float2 f2unpack(ull v) {
    float2 r; asm("mov.b64 {%0,%1},%2;" : "=f"(r.x), "=f"(r.y) : "l"(v)); return r;
}

// ---- device scratch ----
__device__ float g_gamma[MROWS*FF];
__device__ float g_cat  [MROWS*2*FF];
__device__ float g_rlh1 [MROWS*FF];
__device__ float g_corr [MROWS*FF];
__device__ float g_rl   [MROWS*FF];
__device__ float g_q    [MROWS*FF];
__device__ float g_k    [MROWS*FF];
__device__ float g_v    [MROWS*FF];
__device__ float g_av   [MROWS*FF];
__device__ float g_A0   [(size_t)MROWS*512];
__device__ float g_A1   [(size_t)MROWS*512];
__device__ float g_A2   [(size_t)MROWS*512];
__device__ float g_Bp0  [328*512];
__device__ float g_Bp1  [128*512];
__device__ float g_Bp2  [128*512];
__device__ float g_h    [3*2*HH*BB];     // [layer][parity][h][b]
__device__ unsigned g_bar_cnt;
__device__ unsigned g_bar_gen;

// Pack GEMM-ready B matrices (-LAMBDA folded into f gate)
__global__ void pack_kernel(const float* __restrict__ w0,
                            const float* __restrict__ gw0,
                            const float* __restrict__ gw12) {
    int idx = blockIdx.x * blockDim.x + threadIdx.x;
    const int N0 = 328*512;
    if (idx < N0) {
        int k = idx >> 9, n = idx & 511;
        float v;
        if (k < DD) v = w0[(HH + k)*512 + n];
        else {
            int f = k - DD, g = n >> 7, h = n & 127;
            v = gw0[g*16384 + f*128 + h] * (g == 1 ? -LAMBDA : 1.0f);
        }
        g_Bp0[idx] = v;
    } else if (idx < N0 + 65536) {
        int j = idx - N0, f = j >> 9, n = j & 511, g = n >> 7, h = n & 127;
        g_Bp1[j] = gw12[g*16384 + f*128 + h] * (g == 1 ? -LAMBDA : 1.0f);
    } else if (idx < N0 + 2*65536) {
        int j = idx - N0 - 65536, f = j >> 9, n = j & 511, g = n >> 7, h = n & 127;
        g_Bp2[j] = gw12[65536 + g*16384 + f*128 + h] * (g == 1 ? -LAMBDA : 1.0f);
    }
}

// amp/ph embeddings (cat = [ph, amp]) + rlos hidden1
__global__ void ew1_kernel(const float* __restrict__ ampc, const float* __restrict__ phc,
                           const float* __restrict__ rd,
                           const float* __restrict__ aw, const float* __restrict__ ab,
                           const float* __restrict__ pw, const float* __restrict__ pb,
                           const float* __restrict__ w1, const float* __restrict__ b1) {
    int idx = blockIdx.x * blockDim.x + threadIdx.x;
    if (idx >= MROWS*FF) return;
    int r = idx >> 7, f = idx & 127;
    g_cat[r*256 + f]       = tanhf(phc[r]  * pw[f] + pb[f]);
    g_cat[r*256 + 128 + f] = tanhf(ampc[r] * aw[f] + ab[f]);
    g_rlh1[idx] = tanhf(rd[r*2]*w1[f] + rd[r*2+1]*w1[128+f] + b1[f]);
}

__global__ void ew3_kernel() {   // av = sigmoid(dot(q,k)/sqrt(F)) * v
    int r = blockIdx.x, f = threadIdx.x;
    float p = g_q[r*128 + f] * g_k[r*128 + f];
    #pragma unroll
    for (int off = 16; off; off >>= 1) p += __shfl_xor_sync(0xffffffffu, p, off);
    __shared__ float ws[4];
    if ((f & 31) == 0) ws[f >> 5] = p;
    __syncthreads();
    float dot = ws[0] + ws[1] + ws[2] + ws[3];
    float attn = 1.0f / (1.0f + expf(-dot * 0.08838834764831845f));
    g_av[r*128 + f] = attn * g_v[r*128 + f];
}

// fp32 GEMM with packed fma.rn.f32x2. Tile 128x128, 8x8 per-thread.
__global__ __launch_bounds__(256) void gemm_kernel(
    const float* __restrict__ A, const float* __restrict__ Bm,
    const float* __restrict__ bias, float* __restrict__ C,
    int M, int N, int K, int act, int amode, const float* __restrict__ Aux)
{
    __shared__ __align__(16) float As[16][128];
    __shared__ __align__(16) float Bs[16][128];
    const int tid = threadIdx.x;
    const int tx = tid & 15, ty = tid >> 4;
    const int rowBase = blockIdx.y * 128, colBase = blockIdx.x * 128;
    ull acc[8][4] = {};

    const int lm = tid >> 1, lk0 = (tid & 1) * 8;
    const int r = rowBase + lm;
    const int tmod = r & (TT - 1);

    for (int k0 = 0; k0 < K; k0 += 16) {
        #pragma unroll
        for (int i = 0; i < 8; i++) {
            int k = k0 + lk0 + i;
            float v = 0.0f;
            if (k < K) {
                if (amode == 0)      v = A[(size_t)r*K + k];
                else if (amode == 1) v = (tmod == 0) ? 0.0f : A[(size_t)(r-1)*FF + k];
                else {
                    if (k < DD) v = fabsf(Aux[(size_t)r*DD + k]);
                    else        v = (tmod == 0) ? 0.0f : A[(size_t)(r-1)*FF + (k - DD)];
                }
            }
            As[lk0 + i][lm] = v;
        }
        #pragma unroll
        for (int i = 0; i < 2; i++) {
            int f4 = tid + i*256;
            int bk = f4 >> 5, bc = (f4 & 31) * 4;
            float4 v = make_float4(0.f, 0.f, 0.f, 0.f);
            if (k0 + bk < K) v = *(const float4*)&Bm[(size_t)(k0 + bk)*N + colBase + bc];
            *(float4*)&Bs[bk][bc] = v;
        }
        __syncthreads();
        #pragma unroll
        for (int kk = 0; kk < 16; kk++) {
            float4 a0 = *(const float4*)&As[kk][ty*4];
            float4 a1 = *(const float4*)&As[kk][64 + ty*4];
            ulonglong2 b0 = *(const ulonglong2*)&Bs[kk][tx*4];
            ulonglong2 b1 = *(const ulonglong2*)&Bs[kk][64 + tx*4];
            ull ad[8] = {f2dup(a0.x), f2dup(a0.y), f2dup(a0.z), f2dup(a0.w),
                         f2dup(a1.x), f2dup(a1.y), f2dup(a1.z), f2dup(a1.w)};
            ull bd[4] = {b0.x, b0.y, b1.x, b1.y};
            #pragma unroll
            for (int i = 0; i < 8; i++)
                #pragma unroll
                for (int j = 0; j < 4; j++) acc[i][j] = ffma2(ad[i], bd[j], acc[i][j]);
        }
        __syncthreads();
    }

    #pragma unroll
    for (int rh = 0; rh < 2; rh++) {
        #pragma unroll
        for (int i = 0; i < 4; i++) {
            int row = rowBase + rh*64 + ty*4 + i;
            #pragma unroll
            for (int ch = 0; ch < 2; ch++) {
                int col = colBase + ch*64 + tx*4;
                float2 p0 = f2unpack(acc[rh*4 + i][ch*2]);
                float2 p1 = f2unpack(acc[rh*4 + i][ch*2 + 1]);
                float v[4] = {p0.x, p0.y, p1.x, p1.y};
                #pragma unroll
                for (int j = 0; j < 4; j++) {
                    float x = v[j] + (bias ? bias[col + j] : 0.0f);
                    if (act == 1)      x = tanhf(x);
                    else if (act >= 2) x = 1.0f / (1.0f + expf(-x));
                    v[j] = x;
                }
                if (act == 3) {   // beta -> corr blend (A = g_cat, stride 256)
                    #pragma unroll
                    for (int j = 0; j < 4; j++) {
                        float ph = A[(size_t)row*256 + col + j];
                        float am = A[(size_t)row*256 + 128 + col + j];
                        v[j] = v[j]*ph + (1.0f - v[j])*am;
                    }
                }
                *(float4*)&C[(size_t)row*N + col] = make_float4(v[0], v[1], v[2], v[3]);
            }
        }
    }
}

__global__ void bar_init_kernel() { g_bar_cnt = 0u; g_bar_gen = 0u; }

__device__ __forceinline__ void grid_barrier(unsigned* gen) {
    __syncthreads();
    if (threadIdx.x == 0) {
        unsigned target = *gen + 1u;
        __threadfence();
        unsigned old = atomicAdd(&g_bar_cnt, 1u);
        if (old == gridDim.x - 1u) {
            *(volatile unsigned*)&g_bar_cnt = 0u;
            __threadfence();
            atomicExch(&g_bar_gen, target);
        } else {
            while (*(volatile unsigned*)&g_bar_gen < target) { }
        }
        __threadfence();
    }
    __syncthreads();
    *gen += 1u;
}

// Persistent wavefront recurrence: 128 blocks = 8 b-tiles(32) x 16 h-tiles(8).
// 512 threads: k-dimension split in half per thread for latency hiding.
__global__ __launch_bounds__(512, 1) void lstm_kernel(
    const float* __restrict__ w0g, const float* __restrict__ w12g)
{
    extern __shared__ __align__(16) float sm[];
    float* w0_s = sm;                   // [128][32]
    float* w1_s = sm + 4096;            // [256][32]
    float* w2_s = sm + 12288;           // [256][32]
    float* h_s  = sm + 20480;           // [3][128][32]
    float* z_s  = sm + 32768;           // [2 zb][2 kh][32][33]

    const int tid = threadIdx.x;
    const int btile = blockIdx.x & 7, htile = blockIdx.x >> 3;
    const int col = tid & 31;           // gate*8 + h_local
    const int bg  = (tid >> 5) & 7;     // batch quad
    const int kh  = tid >> 8;           // k-half 0/1
    const int ncol = (col >> 3)*128 + htile*8 + (col & 7);
    const int ub = tid & 31, uh = (tid >> 5) & 7;   // update mapping (tid<256)

    for (int idx = tid; idx < 128*32; idx += 512) {
        int k = idx >> 5, c = idx & 31;
        int n = (c >> 3)*128 + htile*8 + (c & 7);
        w0_s[idx] = w0g[k*512 + n];
    }
    for (int idx = tid; idx < 256*32; idx += 512) {
        int k = idx >> 5, c = idx & 31;
        int n = (c >> 3)*128 + htile*8 + (c & 7);
        w1_s[idx] = w12g[k*512 + n];
        w2_s[idx] = w12g[256*512 + k*512 + n];
    }
    {
        int base = blockIdx.x * 1536;
        for (int i = tid; i < 1536; i += 512) g_h[base + i] = 0.0f;
    }

    float cst[3] = {0.0f, 0.0f, 0.0f};
    const float* gA0 = g_A0; const float* gA1 = g_A1; const float* gA2 = g_A2;

    unsigned gen = 0;
    grid_barrier(&gen);

    for (int w = 0; w < TT + 2; w++) {
        const int pp = (w + 1) & 1, cp = w & 1;
        for (int idx = tid; idx < 3*128*32; idx += 512) {
            int l = idx / 4096, rem = idx - l*4096;
            int k = rem >> 5, b = rem & 31;
            h_s[idx] = __ldcg(&g_h[((l*2 + pp)*128 + k)*256 + btile*32 + b]);
        }
        __syncthreads();

        #pragma unroll
        for (int l = 0; l < 3; l++) {
            int s = w - l;
            if (s < 0 || s >= TT) continue;   // uniform across block

            const int zb = l & 1;
            float* zw = z_s + (zb*2 + kh)*32*33;

            ull p01, p23;
            if (kh == 0) {
                const float* gA = (l == 0) ? gA0 : (l == 1) ? gA1 : gA2;
                const float* Ap = gA + (size_t)((btile*32 + bg*4)*TT + s)*512 + ncol;
                p01 = f2pack(Ap[0], Ap[(size_t)TT*512]);
                p23 = f2pack(Ap[(size_t)2*TT*512], Ap[(size_t)3*TT*512]);
            } else { p01 = 0ull; p23 = 0ull; }

            if (l == 0) {
                const float* wb = w0_s + kh*64*32;
                const float* hb = h_s  + kh*64*32;
                #pragma unroll 8
                for (int j = 0; j < 64; j++) {
                    ull wd = f2dup(wb[j*32 + col]);
                    ulonglong2 h2 = *(const ulonglong2*)&hb[j*32 + bg*4];
                    p01 = ffma2(wd, h2.x, p01);
                    p23 = ffma2(wd, h2.y, p23);
                }
            } else {
                const float* wl = (l == 1) ? w1_s : w2_s;
                const float* wb0 = wl + kh*64*32;
                const float* hb0 = h_s + l*4096 + kh*64*32;
                const float* wb1 = wl + 128*32 + kh*64*32;
                const float* hb1 = h_s + (l-1)*4096 + kh*64*32;
                #pragma unroll 8
                for (int j = 0; j < 64; j++) {
                    ull wd = f2dup(wb0[j*32 + col]);
                    ulonglong2 h2 = *(const ulonglong2*)&hb0[j*32 + bg*4];
                    p01 = ffma2(wd, h2.x, p01);
                    p23 = ffma2(wd, h2.y, p23);
                }
                #pragma unroll 8
                for (int j = 0; j < 64; j++) {
                    ull wd = f2dup(wb1[j*32 + col]);
                    ulonglong2 h2 = *(const ulonglong2*)&hb1[j*32 + bg*4];
                    p01 = ffma2(wd, h2.x, p01);
                    p23 = ffma2(wd, h2.y, p23);
                }
            }
            float2 u01 = f2unpack(p01), u23 = f2unpack(p23);
            zw[col*33 + bg*4 + 0] = u01.x;
            zw[col*33 + bg*4 + 1] = u01.y;
            zw[col*33 + bg*4 + 2] = u23.x;
            zw[col*33 + bg*4 + 3] = u23.y;
            __syncthreads();

            if (tid < 256) {
                const float* z0 = z_s + (zb*2 + 0)*32*33;
                const float* z1 = z_s + (zb*2 + 1)*32*33;
                float zi = z0[(0*8 + uh)*33 + ub] + z1[(0*8 + uh)*33 + ub];
                float zf = z0[(1*8 + uh)*33 + ub] + z1[(1*8 + uh)*33 + ub];
                float zc = z0[(2*8 + uh)*33 + ub] + z1[(2*8 + uh)*33 + ub];
                float zo = z0[(3*8 + uh)*33 + ub] + z1[(3*8 + uh)*33 + ub];
                float iv = 1.0f / (1.0f + expf(-zi));
                float fv = 1.0f / (1.0f + expf(-zf));
                float cv = tanhf(zc);
                float ov = 1.0f / (1.0f + expf(-zo));
                cst[l] = fv*cst[l] + iv*cv;
                float hn = ov * tanhf(cst[l]);
                g_h[((l*2 + cp)*128 + htile*8 + uh)*256 + btile*32 + ub] = hn;
            }
            // no trailing sync: z double-buffered; next layer's sync orders reuse
        }
        __threadfence();   // publish this wave's g_h stores before barrier signal
        grid_barrier(&gen);
    }
}

__global__ void out_kernel(const float* __restrict__ rw, const float* __restrict__ rb,
                           float* __restrict__ out) {
    int b = threadIdx.x;
    const int p = (TT + 1) & 1;
    float a0 = rb[0], a1 = rb[1];
    #pragma unroll 4
    for (int h = 0; h < HH; h++) {
        float hv = g_h[((2*2 + p)*128 + h)*256 + b];
        a0 += hv * rw[h*2 + 0];
        a1 += hv * rw[h*2 + 1];
    }
    out[b*2 + 0] = a0;
    out[b*2 + 1] = a1;
}

extern "C" void kernel_launch(void* const* d_in, const int* in_sizes, int n_in,
                              void* d_out, int out_size) {
    (void)in_sizes; (void)n_in; (void)out_size;
    const float* hrrp     = (const float*)d_in[0];
    const float* ampc     = (const float*)d_in[1];
    const float* phc      = (const float*)d_in[2];
    const float* rd       = (const float*)d_in[3];
    const float* f_amp_w  = (const float*)d_in[4];
    const float* f_amp_b  = (const float*)d_in[5];
    const float* f_ph_w   = (const float*)d_in[6];
    const float* f_ph_b   = (const float*)d_in[7];
    const float* f_gate_w = (const float*)d_in[8];
    const float* f_gate_b = (const float*)d_in[9];
    const float* f_rl_w1  = (const float*)d_in[10];
    const float* f_rl_b1  = (const float*)d_in[11];
    const float* f_rl_w2  = (const float*)d_in[12];
    const float* f_rl_b2  = (const float*)d_in[13];
    const float* f_q_w    = (const float*)d_in[14];
    const float* f_q_b    = (const float*)d_in[15];
    const float* f_k_w    = (const float*)d_in[16];
    const float* f_k_b    = (const float*)d_in[17];
    const float* f_v_w    = (const float*)d_in[18];
    const float* f_v_b    = (const float*)d_in[19];
    const float* f_out_w  = (const float*)d_in[20];
    const float* f_out_b  = (const float*)d_in[21];
    const float* base_w0  = (const float*)d_in[22];
    const float* base_b0  = (const float*)d_in[23];
    const float* gam_w0   = (const float*)d_in[24];
    const float* base_w12 = (const float*)d_in[25];
    const float* base_b12 = (const float*)d_in[26];
    const float* gam_w12  = (const float*)d_in[27];
    const float* reg_w    = (const float*)d_in[28];
    const float* reg_b    = (const float*)d_in[29];
    float* out = (float*)d_out;

    float *p_cat, *p_rlh1, *p_corr, *p_rl, *p_q, *p_k, *p_v, *p_av, *p_gamma;
    float *p_A0, *p_A1, *p_A2, *p_Bp0, *p_Bp1, *p_Bp2;
    cudaGetSymbolAddress((void**)&p_cat,   g_cat);
    cudaGetSymbolAddress((void**)&p_rlh1,  g_rlh1);
    cudaGetSymbolAddress((void**)&p_corr,  g_corr);
    cudaGetSymbolAddress((void**)&p_rl,    g_rl);
    cudaGetSymbolAddress((void**)&p_q,     g_q);
    cudaGetSymbolAddress((void**)&p_k,     g_k);
    cudaGetSymbolAddress((void**)&p_v,     g_v);
    cudaGetSymbolAddress((void**)&p_av,    g_av);
    cudaGetSymbolAddress((void**)&p_gamma, g_gamma);
    cudaGetSymbolAddress((void**)&p_A0,    g_A0);
    cudaGetSymbolAddress((void**)&p_A1,    g_A1);
    cudaGetSymbolAddress((void**)&p_A2,    g_A2);
    cudaGetSymbolAddress((void**)&p_Bp0,   g_Bp0);
    cudaGetSymbolAddress((void**)&p_Bp1,   g_Bp1);
    cudaGetSymbolAddress((void**)&p_Bp2,   g_Bp2);

    pack_kernel<<<1168, 256>>>(base_w0, gam_w0, gam_w12);
    ew1_kernel<<<65536, 256>>>(ampc, phc, rd, f_amp_w, f_amp_b, f_ph_w, f_ph_b, f_rl_w1, f_rl_b1);

    dim3 gF(1, 1024), gA(4, 1024);
    gemm_kernel<<<gF, 256>>>(p_cat,  f_gate_w, f_gate_b, p_corr, MROWS, 128, 256, 3, 0, nullptr);
    gemm_kernel<<<gF, 256>>>(p_rlh1, f_rl_w2,  f_rl_b2,  p_rl,   MROWS, 128, 128, 1, 0, nullptr);
    gemm_kernel<<<gF, 256>>>(p_corr, f_q_w,    f_q_b,    p_q,    MROWS, 128, 128, 0, 0, nullptr);
    gemm_kernel<<<gF, 256>>>(p_rl,   f_k_w,    f_k_b,    p_k,    MROWS, 128, 128, 0, 0, nullptr);
    gemm_kernel<<<gF, 256>>>(p_rl,   f_v_w,    f_v_b,    p_v,    MROWS, 128, 128, 0, 0, nullptr);
    ew3_kernel<<<MROWS, 128>>>();
    gemm_kernel<<<gF, 256>>>(p_av,   f_out_w,  f_out_b,  p_gamma, MROWS, 128, 128, 0, 0, nullptr);

    gemm_kernel<<<gA, 256>>>(p_gamma, p_Bp0, base_b0,        p_A0, MROWS, 512, 328, 0, 2, hrrp);
    gemm_kernel<<<gA, 256>>>(p_gamma, p_Bp1, base_b12,       p_A1, MROWS, 512, 128, 0, 1, nullptr);
    gemm_kernel<<<gA, 256>>>(p_gamma, p_Bp2, base_b12 + 512, p_A2, MROWS, 512, 128, 0, 1, nullptr);

    bar_init_kernel<<<1, 1>>>();
    const int SMEM_BYTES = (4096 + 8192 + 8192 + 12288 + 2*2*32*33) * 4;  // 147968
    cudaFuncSetAttribute(lstm_kernel, cudaFuncAttributeMaxDynamicSharedMemorySize, SMEM_BYTES);
    lstm_kernel<<<128, 512, SMEM_BYTES>>>(base_w0, base_w12);
    out_kernel<<<1, 256>>>(reg_w, reg_b, out);
}

// round 16
// speedup vs baseline: 1.5087x; 1.0901x over previous
#include <cuda_runtime.h>
#include <math.h>

#define BB 256
#define TT 512
#define DD 200
#define HH 128
#define FF 128
#define MROWS (BB*TT)
#define LAMBDA 0.5f

typedef unsigned long long ull;

__device__ __forceinline__ ull f2dup(float x) {
    ull r; asm("mov.b64 %0,{%1,%1};" : "=l"(r) : "f"(x)); return r;
}
__device__ __forceinline__ ull f2pack(float x, float y) {
    ull r; asm("mov.b64 %0,{%1,%2};" : "=l"(r) : "f"(x), "f"(y)); return r;
}
__device__ __forceinline__ ull ffma2(ull a, ull b, ull c) {
    ull d; asm("fma.rn.f32x2 %0,%1,%2,%3;" : "=l"(d) : "l"(a), "l"(b), "l"(c)); return d;
}
__device__ __forceinline__ float2 f2unpack(ull v) {
    float2 r; asm("mov.b64 {%0,%1},%2;" : "=f"(r.x), "=f"(r.y) : "l"(v)); return r;
}

// ---- device scratch ----
__device__ float g_gamma[MROWS*FF];
__device__ float g_cat  [MROWS*2*FF];
__device__ float g_rlh1 [MROWS*FF];
__device__ float g_corr [MROWS*FF];
__device__ float g_rl   [MROWS*FF];
__device__ float g_q    [MROWS*FF];
__device__ float g_k    [MROWS*FF];
__device__ float g_v    [MROWS*FF];
__device__ float g_av   [MROWS*FF];
__device__ float g_A0   [(size_t)MROWS*512];
__device__ float g_A1   [(size_t)MROWS*512];
__device__ float g_A2   [(size_t)MROWS*512];
__device__ float g_Bp0  [328*512];
__device__ float g_Bp1  [128*512];
__device__ float g_Bp2  [128*512];
__device__ float g_h    [3*2*HH*BB];     // [layer][parity][h][b]
__device__ unsigned g_bar_cnt;
__device__ unsigned g_bar_gen;

// Pack GEMM-ready B matrices (-LAMBDA folded into f gate)
__global__ void pack_kernel(const float* __restrict__ w0,
                            const float* __restrict__ gw0,
                            const float* __restrict__ gw12) {
    int idx = blockIdx.x * blockDim.x + threadIdx.x;
    const int N0 = 328*512;
    if (idx < N0) {
        int k = idx >> 9, n = idx & 511;
        float v;
        if (k < DD) v = w0[(HH + k)*512 + n];
        else {
            int f = k - DD, g = n >> 7, h = n & 127;
            v = gw0[g*16384 + f*128 + h] * (g == 1 ? -LAMBDA : 1.0f);
        }
        g_Bp0[idx] = v;
    } else if (idx < N0 + 65536) {
        int j = idx - N0, f = j >> 9, n = j & 511, g = n >> 7, h = n & 127;
        g_Bp1[j] = gw12[g*16384 + f*128 + h] * (g == 1 ? -LAMBDA : 1.0f);
    } else if (idx < N0 + 2*65536) {
        int j = idx - N0 - 65536, f = j >> 9, n = j & 511, g = n >> 7, h = n & 127;
        g_Bp2[j] = gw12[65536 + g*16384 + f*128 + h] * (g == 1 ? -LAMBDA : 1.0f);
    }
}

// amp/ph embeddings (cat = [ph, amp]) + rlos hidden1
__global__ void ew1_kernel(const float* __restrict__ ampc, const float* __restrict__ phc,
                           const float* __restrict__ rd,
                           const float* __restrict__ aw, const float* __restrict__ ab,
                           const float* __restrict__ pw, const float* __restrict__ pb,
                           const float* __restrict__ w1, const float* __restrict__ b1) {
    int idx = blockIdx.x * blockDim.x + threadIdx.x;
    if (idx >= MROWS*FF) return;
    int r = idx >> 7, f = idx & 127;
    g_cat[r*256 + f]       = tanhf(phc[r]  * pw[f] + pb[f]);
    g_cat[r*256 + 128 + f] = tanhf(ampc[r] * aw[f] + ab[f]);
    g_rlh1[idx] = tanhf(rd[r*2]*w1[f] + rd[r*2+1]*w1[128+f] + b1[f]);
}

__global__ void ew3_kernel() {   // av = sigmoid(dot(q,k)/sqrt(F)) * v
    int r = blockIdx.x, f = threadIdx.x;
    float p = g_q[r*128 + f] * g_k[r*128 + f];
    #pragma unroll
    for (int off = 16; off; off >>= 1) p += __shfl_xor_sync(0xffffffffu, p, off);
    __shared__ float ws[4];
    if ((f & 31) == 0) ws[f >> 5] = p;
    __syncthreads();
    float dot = ws[0] + ws[1] + ws[2] + ws[3];
    float attn = 1.0f / (1.0f + expf(-dot * 0.08838834764831845f));
    g_av[r*128 + f] = attn * g_v[r*128 + f];
}

// fp32 GEMM with packed fma.rn.f32x2. Tile 128x128, 8x8 per-thread.
__global__ __launch_bounds__(256) void gemm_kernel(
    const float* __restrict__ A, const float* __restrict__ Bm,
    const float* __restrict__ bias, float* __restrict__ C,
    int M, int N, int K, int act, int amode, const float* __restrict__ Aux)
{
    __shared__ __align__(16) float As[16][128];
    __shared__ __align__(16) float Bs[16][128];
    const int tid = threadIdx.x;
    const int tx = tid & 15, ty = tid >> 4;
    const int rowBase = blockIdx.y * 128, colBase = blockIdx.x * 128;
    ull acc[8][4] = {};

    const int lm = tid >> 1, lk0 = (tid & 1) * 8;
    const int r = rowBase + lm;
    const int tmod = r & (TT - 1);

    for (int k0 = 0; k0 < K; k0 += 16) {
        #pragma unroll
        for (int i = 0; i < 8; i++) {
            int k = k0 + lk0 + i;
            float v = 0.0f;
            if (k < K) {
                if (amode == 0)      v = A[(size_t)r*K + k];
                else if (amode == 1) v = (tmod == 0) ? 0.0f : A[(size_t)(r-1)*FF + k];
                else {
                    if (k < DD) v = fabsf(Aux[(size_t)r*DD + k]);
                    else        v = (tmod == 0) ? 0.0f : A[(size_t)(r-1)*FF + (k - DD)];
                }
            }
            As[lk0 + i][lm] = v;
        }
        #pragma unroll
        for (int i = 0; i < 2; i++) {
            int f4 = tid + i*256;
            int bk = f4 >> 5, bc = (f4 & 31) * 4;
            float4 v = make_float4(0.f, 0.f, 0.f, 0.f);
            if (k0 + bk < K) v = *(const float4*)&Bm[(size_t)(k0 + bk)*N + colBase + bc];
            *(float4*)&Bs[bk][bc] = v;
        }
        __syncthreads();
        #pragma unroll
        for (int kk = 0; kk < 16; kk++) {
            float4 a0 = *(const float4*)&As[kk][ty*4];
            float4 a1 = *(const float4*)&As[kk][64 + ty*4];
            ulonglong2 b0 = *(const ulonglong2*)&Bs[kk][tx*4];
            ulonglong2 b1 = *(const ulonglong2*)&Bs[kk][64 + tx*4];
            ull ad[8] = {f2dup(a0.x), f2dup(a0.y), f2dup(a0.z), f2dup(a0.w),
                         f2dup(a1.x), f2dup(a1.y), f2dup(a1.z), f2dup(a1.w)};
            ull bd[4] = {b0.x, b0.y, b1.x, b1.y};
            #pragma unroll
            for (int i = 0; i < 8; i++)
                #pragma unroll
                for (int j = 0; j < 4; j++) acc[i][j] = ffma2(ad[i], bd[j], acc[i][j]);
        }
        __syncthreads();
    }

    #pragma unroll
    for (int rh = 0; rh < 2; rh++) {
        #pragma unroll
        for (int i = 0; i < 4; i++) {
            int row = rowBase + rh*64 + ty*4 + i;
            #pragma unroll
            for (int ch = 0; ch < 2; ch++) {
                int col = colBase + ch*64 + tx*4;
                float2 p0 = f2unpack(acc[rh*4 + i][ch*2]);
                float2 p1 = f2unpack(acc[rh*4 + i][ch*2 + 1]);
                float v[4] = {p0.x, p0.y, p1.x, p1.y};
                #pragma unroll
                for (int j = 0; j < 4; j++) {
                    float x = v[j] + (bias ? bias[col + j] : 0.0f);
                    if (act == 1)      x = tanhf(x);
                    else if (act >= 2) x = 1.0f / (1.0f + expf(-x));
                    v[j] = x;
                }
                if (act == 3) {   // beta -> corr blend (A = g_cat, stride 256)
                    #pragma unroll
                    for (int j = 0; j < 4; j++) {
                        float ph = A[(size_t)row*256 + col + j];
                        float am = A[(size_t)row*256 + 128 + col + j];
                        v[j] = v[j]*ph + (1.0f - v[j])*am;
                    }
                }
                *(float4*)&C[(size_t)row*N + col] = make_float4(v[0], v[1], v[2], v[3]);
            }
        }
    }
}

__global__ void bar_init_kernel() { g_bar_cnt = 0u; g_bar_gen = 0u; }

__device__ __forceinline__ void grid_barrier(unsigned* gen) {
    __syncthreads();
    if (threadIdx.x == 0) {
        unsigned target = *gen + 1u;
        __threadfence();
        unsigned old = atomicAdd(&g_bar_cnt, 1u);
        if (old == gridDim.x - 1u) {
            *(volatile unsigned*)&g_bar_cnt = 0u;
            __threadfence();
            atomicExch(&g_bar_gen, target);
        } else {
            while (*(volatile unsigned*)&g_bar_gen < target) { }
        }
        __threadfence();
    }
    __syncthreads();
    *gen += 1u;
}

// Persistent wavefront recurrence: 128 blocks = 8 b-tiles(32) x 16 h-tiles(8).
// 512 threads = 32 cols x 2 batch-halves(16) x 8 k-splits. 16 batch per thread,
// h via LDS.128 broadcast -> ~102 MACs/smem-cyc (was 64).
__global__ __launch_bounds__(512, 1) void lstm_kernel(
    const float* __restrict__ w0g, const float* __restrict__ w12g)
{
    extern __shared__ __align__(16) float sm[];
    float* w0_s = sm;                   // [128][32]
    float* w1_s = sm + 4096;            // [256][32]
    float* w2_s = sm + 12288;           // [256][32]
    float* h_s  = sm + 20480;           // [3][128][32]
    float* z_s  = sm + 32768;           // [8 kh][32 col][33]

    const int tid = threadIdx.x;
    const int btile = blockIdx.x & 7, htile = blockIdx.x >> 3;
    const int col = tid & 31;           // gate*8 + h_local
    const int bg  = (tid >> 5) & 1;     // batch half (16)
    const int kh  = tid >> 6;           // k-split 0..7
    const int ncol = (col >> 3)*128 + htile*8 + (col & 7);
    const int ub = tid & 31, uh = (tid >> 5) & 7;   // update mapping (tid<256)

    for (int idx = tid; idx < 128*32; idx += 512) {
        int k = idx >> 5, c = idx & 31;
        int n = (c >> 3)*128 + htile*8 + (c & 7);
        w0_s[idx] = w0g[k*512 + n];
    }
    for (int idx = tid; idx < 256*32; idx += 512) {
        int k = idx >> 5, c = idx & 31;
        int n = (c >> 3)*128 + htile*8 + (c & 7);
        w1_s[idx] = w12g[k*512 + n];
        w2_s[idx] = w12g[256*512 + k*512 + n];
    }
    {
        int base = blockIdx.x * 1536;
        for (int i = tid; i < 1536; i += 512) g_h[base + i] = 0.0f;
    }

    float cst[3] = {0.0f, 0.0f, 0.0f};
    const float* gA0 = g_A0; const float* gA1 = g_A1; const float* gA2 = g_A2;

    unsigned gen = 0;
    grid_barrier(&gen);

    for (int w = 0; w < TT + 2; w++) {
        const int pp = (w + 1) & 1, cp = w & 1;
        // stage prev-parity h (all 3 layers), vectorized float4
        for (int i4 = tid; i4 < 3072; i4 += 512) {
            int l = i4 >> 10, rem = i4 & 1023;
            int k = rem >> 3, b4 = (rem & 7) * 4;
            float4 v = __ldcg((const float4*)&g_h[((l*2 + pp)*128 + k)*256 + btile*32 + b4]);
            *(float4*)&h_s[l*4096 + k*32 + b4] = v;
        }
        __syncthreads();

        #pragma unroll
        for (int l = 0; l < 3; l++) {
            int s = w - l;
            if (s < 0 || s >= TT) continue;   // uniform across block

            ull acc[8];
            #pragma unroll
            for (int m = 0; m < 8; m++) acc[m] = 0ull;

            if (kh == 0) {   // A-init carried by kh==0 warps only (static indices)
                const float* gA = (l == 0) ? gA0 : (l == 1) ? gA1 : gA2;
                const float* Ab = gA + (size_t)s*512 + ncol;
                #pragma unroll
                for (int m = 0; m < 8; m++) {
                    int b0 = btile*32 + bg*16 + 2*m;
                    float x = Ab[(size_t)(b0    )*TT*512];
                    float y = Ab[(size_t)(b0 + 1)*TT*512];
                    acc[m] = f2pack(x, y);
                }
            }

            if (l == 0) {
                const float* hb = h_s + bg*16;
                #pragma unroll 4
                for (int j = 0; j < 16; j++) {
                    int k = kh*16 + j;
                    ull wd = f2dup(w0_s[k*32 + col]);
                    const float* hp = hb + k*32;
                    ulonglong2 q0 = *(const ulonglong2*)(hp);
                    ulonglong2 q1 = *(const ulonglong2*)(hp + 4);
                    ulonglong2 q2 = *(const ulonglong2*)(hp + 8);
                    ulonglong2 q3 = *(const ulonglong2*)(hp + 12);
                    acc[0] = ffma2(wd, q0.x, acc[0]); acc[1] = ffma2(wd, q0.y, acc[1]);
                    acc[2] = ffma2(wd, q1.x, acc[2]); acc[3] = ffma2(wd, q1.y, acc[3]);
                    acc[4] = ffma2(wd, q2.x, acc[4]); acc[5] = ffma2(wd, q2.y, acc[5]);
                    acc[6] = ffma2(wd, q3.x, acc[6]); acc[7] = ffma2(wd, q3.y, acc[7]);
                }
            } else {
                const float* wl = (l == 1) ? w1_s : w2_s;
                const float* hown = h_s + l*4096 + bg*16;
                const float* hlow = h_s + (l-1)*4096 + bg*16;
                #pragma unroll 4
                for (int j = 0; j < 16; j++) {
                    int k = kh*16 + j;
                    ull wd = f2dup(wl[k*32 + col]);
                    const float* hp = hown + k*32;
                    ulonglong2 q0 = *(const ulonglong2*)(hp);
                    ulonglong2 q1 = *(const ulonglong2*)(hp + 4);
                    ulonglong2 q2 = *(const ulonglong2*)(hp + 8);
                    ulonglong2 q3 = *(const ulonglong2*)(hp + 12);
                    acc[0] = ffma2(wd, q0.x, acc[0]); acc[1] = ffma2(wd, q0.y, acc[1]);
                    acc[2] = ffma2(wd, q1.x, acc[2]); acc[3] = ffma2(wd, q1.y, acc[3]);
                    acc[4] = ffma2(wd, q2.x, acc[4]); acc[5] = ffma2(wd, q2.y, acc[5]);
                    acc[6] = ffma2(wd, q3.x, acc[6]); acc[7] = ffma2(wd, q3.y, acc[7]);
                }
                #pragma unroll 4
                for (int j = 0; j < 16; j++) {
                    int k = kh*16 + j;
                    ull wd = f2dup(wl[(128 + k)*32 + col]);
                    const float* hp = hlow + k*32;
                    ulonglong2 q0 = *(const ulonglong2*)(hp);
                    ulonglong2 q1 = *(const ulonglong2*)(hp + 4);
                    ulonglong2 q2 = *(const ulonglong2*)(hp + 8);
                    ulonglong2 q3 = *(const ulonglong2*)(hp + 12);
                    acc[0] = ffma2(wd, q0.x, acc[0]); acc[1] = ffma2(wd, q0.y, acc[1]);
                    acc[2] = ffma2(wd, q1.x, acc[2]); acc[3] = ffma2(wd, q1.y, acc[3]);
                    acc[4] = ffma2(wd, q2.x, acc[4]); acc[5] = ffma2(wd, q2.y, acc[5]);
                    acc[6] = ffma2(wd, q3.x, acc[6]); acc[7] = ffma2(wd, q3.y, acc[7]);
                }
            }

            // store partials: z_s[kh][col][bg*16 + 0..15]
            {
                float* zp = z_s + kh*(32*33) + col*33 + bg*16;
                #pragma unroll
                for (int m = 0; m < 8; m++) {
                    float2 u = f2unpack(acc[m]);
                    zp[2*m]     = u.x;
                    zp[2*m + 1] = u.y;
                }
            }
            __syncthreads();

            if (tid < 256) {
                float zg[4];
                #pragma unroll
                for (int g = 0; g < 4; g++) {
                    const float* zr = z_s + (g*8 + uh)*33 + ub;
                    float sum = zr[0];
                    #pragma unroll
                    for (int q = 1; q < 8; q++) sum += zr[q*(32*33)];
                    zg[g] = sum;
                }
                float iv = 1.0f / (1.0f + expf(-zg[0]));
                float fv = 1.0f / (1.0f + expf(-zg[1]));
                float cv = tanhf(zg[2]);
                float ov = 1.0f / (1.0f + expf(-zg[3]));
                cst[l] = fv*cst[l] + iv*cv;
                float hn = ov * tanhf(cst[l]);
                g_h[((l*2 + cp)*128 + htile*8 + uh)*256 + btile*32 + ub] = hn;
            }
            __syncthreads();
        }
        __threadfence();   // publish g_h before barrier signal
        grid_barrier(&gen);
    }
}

__global__ void out_kernel(const float* __restrict__ rw, const float* __restrict__ rb,
                           float* __restrict__ out) {
    int b = threadIdx.x;
    const int p = (TT + 1) & 1;
    float a0 = rb[0], a1 = rb[1];
    #pragma unroll 4
    for (int h = 0; h < HH; h++) {
        float hv = g_h[((2*2 + p)*128 + h)*256 + b];
        a0 += hv * rw[h*2 + 0];
        a1 += hv * rw[h*2 + 1];
    }
    out[b*2 + 0] = a0;
    out[b*2 + 1] = a1;
}

extern "C" void kernel_launch(void* const* d_in, const int* in_sizes, int n_in,
                              void* d_out, int out_size) {
    (void)in_sizes; (void)n_in; (void)out_size;
    const float* hrrp     = (const float*)d_in[0];
    const float* ampc     = (const float*)d_in[1];
    const float* phc      = (const float*)d_in[2];
    const float* rd       = (const float*)d_in[3];
    const float* f_amp_w  = (const float*)d_in[4];
    const float* f_amp_b  = (const float*)d_in[5];
    const float* f_ph_w   = (const float*)d_in[6];
    const float* f_ph_b   = (const float*)d_in[7];
    const float* f_gate_w = (const float*)d_in[8];
    const float* f_gate_b = (const float*)d_in[9];
    const float* f_rl_w1  = (const float*)d_in[10];
    const float* f_rl_b1  = (const float*)d_in[11];
    const float* f_rl_w2  = (const float*)d_in[12];
    const float* f_rl_b2  = (const float*)d_in[13];
    const float* f_q_w    = (const float*)d_in[14];
    const float* f_q_b    = (const float*)d_in[15];
    const float* f_k_w    = (const float*)d_in[16];
    const float* f_k_b    = (const float*)d_in[17];
    const float* f_v_w    = (const float*)d_in[18];
    const float* f_v_b    = (const float*)d_in[19];
    const float* f_out_w  = (const float*)d_in[20];
    const float* f_out_b  = (const float*)d_in[21];
    const float* base_w0  = (const float*)d_in[22];
    const float* base_b0  = (const float*)d_in[23];
    const float* gam_w0   = (const float*)d_in[24];
    const float* base_w12 = (const float*)d_in[25];
    const float* base_b12 = (const float*)d_in[26];
    const float* gam_w12  = (const float*)d_in[27];
    const float* reg_w    = (const float*)d_in[28];
    const float* reg_b    = (const float*)d_in[29];
    float* out = (float*)d_out;

    float *p_cat, *p_rlh1, *p_corr, *p_rl, *p_q, *p_k, *p_v, *p_av, *p_gamma;
    float *p_A0, *p_A1, *p_A2, *p_Bp0, *p_Bp1, *p_Bp2;
    cudaGetSymbolAddress((void**)&p_cat,   g_cat);
    cudaGetSymbolAddress((void**)&p_rlh1,  g_rlh1);
    cudaGetSymbolAddress((void**)&p_corr,  g_corr);
    cudaGetSymbolAddress((void**)&p_rl,    g_rl);
    cudaGetSymbolAddress((void**)&p_q,     g_q);
    cudaGetSymbolAddress((void**)&p_k,     g_k);
    cudaGetSymbolAddress((void**)&p_v,     g_v);
    cudaGetSymbolAddress((void**)&p_av,    g_av);
    cudaGetSymbolAddress((void**)&p_gamma, g_gamma);
    cudaGetSymbolAddress((void**)&p_A0,    g_A0);
    cudaGetSymbolAddress((void**)&p_A1,    g_A1);
    cudaGetSymbolAddress((void**)&p_A2,    g_A2);
    cudaGetSymbolAddress((void**)&p_Bp0,   g_Bp0);
    cudaGetSymbolAddress((void**)&p_Bp1,   g_Bp1);
    cudaGetSymbolAddress((void**)&p_Bp2,   g_Bp2);

    pack_kernel<<<1168, 256>>>(base_w0, gam_w0, gam_w12);
    ew1_kernel<<<65536, 256>>>(ampc, phc, rd, f_amp_w, f_amp_b, f_ph_w, f_ph_b, f_rl_w1, f_rl_b1);

    dim3 gF(1, 1024), gA(4, 1024);
    gemm_kernel<<<gF, 256>>>(p_cat,  f_gate_w, f_gate_b, p_corr, MROWS, 128, 256, 3, 0, nullptr);
    gemm_kernel<<<gF, 256>>>(p_rlh1, f_rl_w2,  f_rl_b2,  p_rl,   MROWS, 128, 128, 1, 0, nullptr);
    gemm_kernel<<<gF, 256>>>(p_corr, f_q_w,    f_q_b,    p_q,    MROWS, 128, 128, 0, 0, nullptr);
    gemm_kernel<<<gF, 256>>>(p_rl,   f_k_w,    f_k_b,    p_k,    MROWS, 128, 128, 0, 0, nullptr);
    gemm_kernel<<<gF, 256>>>(p_rl,   f_v_w,    f_v_b,    p_v,    MROWS, 128, 128, 0, 0, nullptr);
    ew3_kernel<<<MROWS, 128>>>();
    gemm_kernel<<<gF, 256>>>(p_av,   f_out_w,  f_out_b,  p_gamma, MROWS, 128, 128, 0, 0, nullptr);

    gemm_kernel<<<gA, 256>>>(p_gamma, p_Bp0, base_b0,        p_A0, MROWS, 512, 328, 0, 2, hrrp);
    gemm_kernel<<<gA, 256>>>(p_gamma, p_Bp1, base_b12,       p_A1, MROWS, 512, 128, 0, 1, nullptr);
    gemm_kernel<<<gA, 256>>>(p_gamma, p_Bp2, base_b12 + 512, p_A2, MROWS, 512, 128, 0, 1, nullptr);

    bar_init_kernel<<<1, 1>>>();
    const int SMEM_BYTES = (4096 + 8192 + 8192 + 12288 + 8*32*33) * 4;  // 164864
    cudaFuncSetAttribute(lstm_kernel, cudaFuncAttributeMaxDynamicSharedMemorySize, SMEM_BYTES);
    lstm_kernel<<<128, 512, SMEM_BYTES>>>(base_w0, base_w12);
    out_kernel<<<1, 256>>>(reg_w, reg_b, out);
}

// round 17
// speedup vs baseline: 1.5620x; 1.0353x over previous
#include <cuda_runtime.h>
#include <math.h>

#define BB 256
#define TT 512
#define DD 200
#define HH 128
#define FF 128
#define MROWS (BB*TT)
#define LAMBDA 0.5f

typedef unsigned long long ull;

__device__ __forceinline__ ull f2dup(float x) {
    ull r; asm("mov.b64 %0,{%1,%1};" : "=l"(r) : "f"(x)); return r;
}
__device__ __forceinline__ ull f2pack(float x, float y) {
    ull r; asm("mov.b64 %0,{%1,%2};" : "=l"(r) : "f"(x), "f"(y)); return r;
}
__device__ __forceinline__ ull ffma2(ull a, ull b, ull c) {
    ull d; asm("fma.rn.f32x2 %0,%1,%2,%3;" : "=l"(d) : "l"(a), "l"(b), "l"(c)); return d;
}
__device__ __forceinline__ ull fadd2(ull a, ull b) {
    ull d; asm("add.rn.f32x2 %0,%1,%2;" : "=l"(d) : "l"(a), "l"(b)); return d;
}
__device__ __forceinline__ float2 f2unpack(ull v) {
    float2 r; asm("mov.b64 {%0,%1},%2;" : "=f"(r.x), "=f"(r.y) : "l"(v)); return r;
}

// ---- device scratch ----
__device__ float g_gamma[MROWS*FF];
__device__ float g_cat  [MROWS*2*FF];
__device__ float g_rlh1 [MROWS*FF];
__device__ float g_corr [MROWS*FF];
__device__ float g_rl   [MROWS*FF];
__device__ float g_q    [MROWS*FF];
__device__ float g_k    [MROWS*FF];
__device__ float g_v    [MROWS*FF];
__device__ float g_av   [MROWS*FF];
__device__ float g_A0   [(size_t)MROWS*512];
__device__ float g_A1   [(size_t)MROWS*512];
__device__ float g_A2   [(size_t)MROWS*512];
__device__ float g_Bp0  [328*512];
__device__ float g_Bp1  [128*512];
__device__ float g_Bp2  [128*512];
__device__ float g_h    [3*2*HH*BB];     // [layer][parity][h][b]
__device__ unsigned g_bcnt[8*32];        // per-btile barrier counters (128B padded)
__device__ unsigned g_bgen[8*32];

// Pack GEMM-ready B matrices (-LAMBDA folded into f gate)
__global__ void pack_kernel(const float* __restrict__ w0,
                            const float* __restrict__ gw0,
                            const float* __restrict__ gw12) {
    int idx = blockIdx.x * blockDim.x + threadIdx.x;
    const int N0 = 328*512;
    if (idx < N0) {
        int k = idx >> 9, n = idx & 511;
        float v;
        if (k < DD) v = w0[(HH + k)*512 + n];
        else {
            int f = k - DD, g = n >> 7, h = n & 127;
            v = gw0[g*16384 + f*128 + h] * (g == 1 ? -LAMBDA : 1.0f);
        }
        g_Bp0[idx] = v;
    } else if (idx < N0 + 65536) {
        int j = idx - N0, f = j >> 9, n = j & 511, g = n >> 7, h = n & 127;
        g_Bp1[j] = gw12[g*16384 + f*128 + h] * (g == 1 ? -LAMBDA : 1.0f);
    } else if (idx < N0 + 2*65536) {
        int j = idx - N0 - 65536, f = j >> 9, n = j & 511, g = n >> 7, h = n & 127;
        g_Bp2[j] = gw12[65536 + g*16384 + f*128 + h] * (g == 1 ? -LAMBDA : 1.0f);
    }
}

// amp/ph embeddings (cat = [ph, amp]) + rlos hidden1
__global__ void ew1_kernel(const float* __restrict__ ampc, const float* __restrict__ phc,
                           const float* __restrict__ rd,
                           const float* __restrict__ aw, const float* __restrict__ ab,
                           const float* __restrict__ pw, const float* __restrict__ pb,
                           const float* __restrict__ w1, const float* __restrict__ b1) {
    int idx = blockIdx.x * blockDim.x + threadIdx.x;
    if (idx >= MROWS*FF) return;
    int r = idx >> 7, f = idx & 127;
    g_cat[r*256 + f]       = tanhf(phc[r]  * pw[f] + pb[f]);
    g_cat[r*256 + 128 + f] = tanhf(ampc[r] * aw[f] + ab[f]);
    g_rlh1[idx] = tanhf(rd[r*2]*w1[f] + rd[r*2+1]*w1[128+f] + b1[f]);
}

__global__ void ew3_kernel() {   // av = sigmoid(dot(q,k)/sqrt(F)) * v
    int r = blockIdx.x, f = threadIdx.x;
    float p = g_q[r*128 + f] * g_k[r*128 + f];
    #pragma unroll
    for (int off = 16; off; off >>= 1) p += __shfl_xor_sync(0xffffffffu, p, off);
    __shared__ float ws[4];
    if ((f & 31) == 0) ws[f >> 5] = p;
    __syncthreads();
    float dot = ws[0] + ws[1] + ws[2] + ws[3];
    float attn = 1.0f / (1.0f + expf(-dot * 0.08838834764831845f));
    g_av[r*128 + f] = attn * g_v[r*128 + f];
}

// fp32 GEMM with packed fma.rn.f32x2. Tile 128x128, 8x8 per-thread.
__global__ __launch_bounds__(256) void gemm_kernel(
    const float* __restrict__ A, const float* __restrict__ Bm,
    const float* __restrict__ bias, float* __restrict__ C,
    int M, int N, int K, int act, int amode, const float* __restrict__ Aux)
{
    __shared__ __align__(16) float As[16][128];
    __shared__ __align__(16) float Bs[16][128];
    const int tid = threadIdx.x;
    const int tx = tid & 15, ty = tid >> 4;
    const int rowBase = blockIdx.y * 128, colBase = blockIdx.x * 128;
    ull acc[8][4] = {};

    const int lm = tid >> 1, lk0 = (tid & 1) * 8;
    const int r = rowBase + lm;
    const int tmod = r & (TT - 1);

    for (int k0 = 0; k0 < K; k0 += 16) {
        #pragma unroll
        for (int i = 0; i < 8; i++) {
            int k = k0 + lk0 + i;
            float v = 0.0f;
            if (k < K) {
                if (amode == 0)      v = A[(size_t)r*K + k];
                else if (amode == 1) v = (tmod == 0) ? 0.0f : A[(size_t)(r-1)*FF + k];
                else {
                    if (k < DD) v = fabsf(Aux[(size_t)r*DD + k]);
                    else        v = (tmod == 0) ? 0.0f : A[(size_t)(r-1)*FF + (k - DD)];
                }
            }
            As[lk0 + i][lm] = v;
        }
        #pragma unroll
        for (int i = 0; i < 2; i++) {
            int f4 = tid + i*256;
            int bk = f4 >> 5, bc = (f4 & 31) * 4;
            float4 v = make_float4(0.f, 0.f, 0.f, 0.f);
            if (k0 + bk < K) v = *(const float4*)&Bm[(size_t)(k0 + bk)*N + colBase + bc];
            *(float4*)&Bs[bk][bc] = v;
        }
        __syncthreads();
        #pragma unroll
        for (int kk = 0; kk < 16; kk++) {
            float4 a0 = *(const float4*)&As[kk][ty*4];
            float4 a1 = *(const float4*)&As[kk][64 + ty*4];
            ulonglong2 b0 = *(const ulonglong2*)&Bs[kk][tx*4];
            ulonglong2 b1 = *(const ulonglong2*)&Bs[kk][64 + tx*4];
            ull ad[8] = {f2dup(a0.x), f2dup(a0.y), f2dup(a0.z), f2dup(a0.w),
                         f2dup(a1.x), f2dup(a1.y), f2dup(a1.z), f2dup(a1.w)};
            ull bd[4] = {b0.x, b0.y, b1.x, b1.y};
            #pragma unroll
            for (int i = 0; i < 8; i++)
                #pragma unroll
                for (int j = 0; j < 4; j++) acc[i][j] = ffma2(ad[i], bd[j], acc[i][j]);
        }
        __syncthreads();
    }

    #pragma unroll
    for (int rh = 0; rh < 2; rh++) {
        #pragma unroll
        for (int i = 0; i < 4; i++) {
            int row = rowBase + rh*64 + ty*4 + i;
            #pragma unroll
            for (int ch = 0; ch < 2; ch++) {
                int col = colBase + ch*64 + tx*4;
                float2 p0 = f2unpack(acc[rh*4 + i][ch*2]);
                float2 p1 = f2unpack(acc[rh*4 + i][ch*2 + 1]);
                float v[4] = {p0.x, p0.y, p1.x, p1.y};
                #pragma unroll
                for (int j = 0; j < 4; j++) {
                    float x = v[j] + (bias ? bias[col + j] : 0.0f);
                    if (act == 1)      x = tanhf(x);
                    else if (act >= 2) x = 1.0f / (1.0f + expf(-x));
                    v[j] = x;
                }
                if (act == 3) {   // beta -> corr blend (A = g_cat, stride 256)
                    #pragma unroll
                    for (int j = 0; j < 4; j++) {
                        float ph = A[(size_t)row*256 + col + j];
                        float am = A[(size_t)row*256 + 128 + col + j];
                        v[j] = v[j]*ph + (1.0f - v[j])*am;
                    }
                }
                *(float4*)&C[(size_t)row*N + col] = make_float4(v[0], v[1], v[2], v[3]);
            }
        }
    }
}

__global__ void bar_init_kernel() {
    int i = threadIdx.x;
    if (i < 8*32) { g_bcnt[i] = 0u; g_bgen[i] = 0u; }
}

// 16-block barrier per btile group
__device__ __forceinline__ void group_barrier(int grp, unsigned* gen) {
    __syncthreads();
    if (threadIdx.x == 0) {
        unsigned target = *gen + 1u;
        __threadfence();
        unsigned old = atomicAdd(&g_bcnt[grp*32], 1u);
        if (old == 15u) {
            *(volatile unsigned*)&g_bcnt[grp*32] = 0u;
            __threadfence();
            atomicExch(&g_bgen[grp*32], target);
        } else {
            while (*(volatile unsigned*)&g_bgen[grp*32] < target) { }
        }
        __threadfence();
    }
    __syncthreads();
    *gen += 1u;
}

// Persistent wavefront recurrence: 128 blocks = 8 b-tiles(32) x 16 h-tiles(8).
// 512 threads = 32 cols x 2 batch-halves(16) x 8 k-splits.
// Merged phases: layers {0,1} compute+update, then layer {2} (z aliased on z0).
__global__ __launch_bounds__(512, 1) void lstm_kernel(
    const float* __restrict__ w0g, const float* __restrict__ w12g)
{
    extern __shared__ __align__(16) float sm[];
    float* w0_s = sm;                   // [128][32]
    float* w1_s = sm + 4096;            // [256][32]
    float* w2_s = sm + 12288;           // [256][32]
    float* h_s  = sm + 20480;           // [3][128][32]
    float* z0_s = sm + 32768;           // [8][32][33]
    float* z1_s = sm + 41216;           // [8][32][33]
    float* z2_s = z0_s;                 // alias (guarded by extra sync)

    const int tid = threadIdx.x;
    const int btile = blockIdx.x & 7, htile = blockIdx.x >> 3;
    const int col = tid & 31;
    const int bg  = (tid >> 5) & 1;
    const int kh  = tid >> 6;
    const int ncol = (col >> 3)*128 + htile*8 + (col & 7);
    const int ub = tid & 31, uh = (tid >> 5) & 7;

    for (int idx = tid; idx < 128*32; idx += 512) {
        int k = idx >> 5, c = idx & 31;
        int n = (c >> 3)*128 + htile*8 + (c & 7);
        w0_s[idx] = w0g[k*512 + n];
    }
    for (int idx = tid; idx < 256*32; idx += 512) {
        int k = idx >> 5, c = idx & 31;
        int n = (c >> 3)*128 + htile*8 + (c & 7);
        w1_s[idx] = w12g[k*512 + n];
        w2_s[idx] = w12g[256*512 + k*512 + n];
    }
    {
        int base = blockIdx.x * 1536;
        for (int i = tid; i < 1536; i += 512) g_h[base + i] = 0.0f;
    }

    float cst[3] = {0.0f, 0.0f, 0.0f};
    unsigned gen = 0;
    group_barrier(btile, &gen);

    for (int w = 0; w < TT + 2; w++) {
        const int pp = (w + 1) & 1, cp = w & 1;
        for (int i4 = tid; i4 < 3072; i4 += 512) {
            int l = i4 >> 10, rem = i4 & 1023;
            int k = rem >> 3, b4 = (rem & 7) * 4;
            float4 v = __ldcg((const float4*)&g_h[((l*2 + pp)*128 + k)*256 + btile*32 + b4]);
            *(float4*)&h_s[l*4096 + k*32 + b4] = v;
        }
        __syncthreads();

        const bool act0 = (w < TT);
        const bool act1 = (w >= 1) && (w - 1 < TT);
        const bool act2 = (w >= 2) && (w - 2 < TT);

        // ---- layer 0 compute ----
        if (act0) {
            float ax[16];
            if (kh == 0) {
                const float* Ab = g_A0 + (size_t)w*512 + ncol;
                #pragma unroll
                for (int m = 0; m < 8; m++) {
                    int b0 = btile*32 + bg*16 + 2*m;
                    ax[2*m]   = Ab[(size_t)b0*TT*512];
                    ax[2*m+1] = Ab[(size_t)(b0+1)*TT*512];
                }
            }
            ull acc[8] = {};
            const float* hb = h_s + bg*16;
            #pragma unroll 4
            for (int j = 0; j < 16; j++) {
                int k = kh*16 + j;
                ull wd = f2dup(w0_s[k*32 + col]);
                const float* hp = hb + k*32;
                ulonglong2 q0 = *(const ulonglong2*)(hp);
                ulonglong2 q1 = *(const ulonglong2*)(hp + 4);
                ulonglong2 q2 = *(const ulonglong2*)(hp + 8);
                ulonglong2 q3 = *(const ulonglong2*)(hp + 12);
                acc[0] = ffma2(wd, q0.x, acc[0]); acc[1] = ffma2(wd, q0.y, acc[1]);
                acc[2] = ffma2(wd, q1.x, acc[2]); acc[3] = ffma2(wd, q1.y, acc[3]);
                acc[4] = ffma2(wd, q2.x, acc[4]); acc[5] = ffma2(wd, q2.y, acc[5]);
                acc[6] = ffma2(wd, q3.x, acc[6]); acc[7] = ffma2(wd, q3.y, acc[7]);
            }
            if (kh == 0) {
                #pragma unroll
                for (int m = 0; m < 8; m++) acc[m] = fadd2(acc[m], f2pack(ax[2*m], ax[2*m+1]));
            }
            float* zp = z0_s + kh*(32*33) + col*33 + bg*16;
            #pragma unroll
            for (int m = 0; m < 8; m++) {
                float2 u = f2unpack(acc[m]);
                zp[2*m] = u.x; zp[2*m + 1] = u.y;
            }
        }

        // ---- layer 1 compute ----
        if (act1) {
            float ax[16];
            if (kh == 0) {
                const float* Ab = g_A1 + (size_t)(w-1)*512 + ncol;
                #pragma unroll
                for (int m = 0; m < 8; m++) {
                    int b0 = btile*32 + bg*16 + 2*m;
                    ax[2*m]   = Ab[(size_t)b0*TT*512];
                    ax[2*m+1] = Ab[(size_t)(b0+1)*TT*512];
                }
            }
            ull acc[8] = {};
            const float* hown = h_s + 4096 + bg*16;
            const float* hlow = h_s + bg*16;
            #pragma unroll 4
            for (int j = 0; j < 16; j++) {
                int k = kh*16 + j;
                ull wd = f2dup(w1_s[k*32 + col]);
                const float* hp = hown + k*32;
                ulonglong2 q0 = *(const ulonglong2*)(hp);
                ulonglong2 q1 = *(const ulonglong2*)(hp + 4);
                ulonglong2 q2 = *(const ulonglong2*)(hp + 8);
                ulonglong2 q3 = *(const ulonglong2*)(hp + 12);
                acc[0] = ffma2(wd, q0.x, acc[0]); acc[1] = ffma2(wd, q0.y, acc[1]);
                acc[2] = ffma2(wd, q1.x, acc[2]); acc[3] = ffma2(wd, q1.y, acc[3]);
                acc[4] = ffma2(wd, q2.x, acc[4]); acc[5] = ffma2(wd, q2.y, acc[5]);
                acc[6] = ffma2(wd, q3.x, acc[6]); acc[7] = ffma2(wd, q3.y, acc[7]);
            }
            #pragma unroll 4
            for (int j = 0; j < 16; j++) {
                int k = kh*16 + j;
                ull wd = f2dup(w1_s[(128 + k)*32 + col]);
                const float* hp = hlow + k*32;
                ulonglong2 q0 = *(const ulonglong2*)(hp);
                ulonglong2 q1 = *(const ulonglong2*)(hp + 4);
                ulonglong2 q2 = *(const ulonglong2*)(hp + 8);
                ulonglong2 q3 = *(const ulonglong2*)(hp + 12);
                acc[0] = ffma2(wd, q0.x, acc[0]); acc[1] = ffma2(wd, q0.y, acc[1]);
                acc[2] = ffma2(wd, q1.x, acc[2]); acc[3] = ffma2(wd, q1.y, acc[3]);
                acc[4] = ffma2(wd, q2.x, acc[4]); acc[5] = ffma2(wd, q2.y, acc[5]);
                acc[6] = ffma2(wd, q3.x, acc[6]); acc[7] = ffma2(wd, q3.y, acc[7]);
            }
            if (kh == 0) {
                #pragma unroll
                for (int m = 0; m < 8; m++) acc[m] = fadd2(acc[m], f2pack(ax[2*m], ax[2*m+1]));
            }
            float* zp = z1_s + kh*(32*33) + col*33 + bg*16;
            #pragma unroll
            for (int m = 0; m < 8; m++) {
                float2 u = f2unpack(acc[m]);
                zp[2*m] = u.x; zp[2*m + 1] = u.y;
            }
        }
        __syncthreads();

        // ---- update layers 0,1 ----
        if (tid < 256) {
            #pragma unroll
            for (int l = 0; l < 2; l++) {
                if (l == 0 ? !act0 : !act1) continue;
                const float* zb = (l == 0) ? z0_s : z1_s;
                float zg[4];
                #pragma unroll
                for (int g = 0; g < 4; g++) {
                    const float* zr = zb + (g*8 + uh)*33 + ub;
                    float sum = zr[0];
                    #pragma unroll
                    for (int q = 1; q < 8; q++) sum += zr[q*(32*33)];
                    zg[g] = sum;
                }
                float iv = 1.0f / (1.0f + expf(-zg[0]));
                float fv = 1.0f / (1.0f + expf(-zg[1]));
                float cv = tanhf(zg[2]);
                float ov = 1.0f / (1.0f + expf(-zg[3]));
                cst[l] = fv*cst[l] + iv*cv;
                float hn = ov * tanhf(cst[l]);
                g_h[((l*2 + cp)*128 + htile*8 + uh)*256 + btile*32 + ub] = hn;
            }
        }

        // ---- layer 2 compute (z stores deferred past sync; z aliases z0) ----
        ull acc2[8];
        if (act2) {
            float ax[16];
            if (kh == 0) {
                const float* Ab = g_A2 + (size_t)(w-2)*512 + ncol;
                #pragma unroll
                for (int m = 0; m < 8; m++) {
                    int b0 = btile*32 + bg*16 + 2*m;
                    ax[2*m]   = Ab[(size_t)b0*TT*512];
                    ax[2*m+1] = Ab[(size_t)(b0+1)*TT*512];
                }
            }
            #pragma unroll
            for (int m = 0; m < 8; m++) acc2[m] = 0ull;
            const float* hown = h_s + 2*4096 + bg*16;
            const float* hlow = h_s + 4096 + bg*16;
            #pragma unroll 4
            for (int j = 0; j < 16; j++) {
                int k = kh*16 + j;
                ull wd = f2dup(w2_s[k*32 + col]);
                const float* hp = hown + k*32;
                ulonglong2 q0 = *(const ulonglong2*)(hp);
                ulonglong2 q1 = *(const ulonglong2*)(hp + 4);
                ulonglong2 q2 = *(const ulonglong2*)(hp + 8);
                ulonglong2 q3 = *(const ulonglong2*)(hp + 12);
                acc2[0] = ffma2(wd, q0.x, acc2[0]); acc2[1] = ffma2(wd, q0.y, acc2[1]);
                acc2[2] = ffma2(wd, q1.x, acc2[2]); acc2[3] = ffma2(wd, q1.y, acc2[3]);
                acc2[4] = ffma2(wd, q2.x, acc2[4]); acc2[5] = ffma2(wd, q2.y, acc2[5]);
                acc2[6] = ffma2(wd, q3.x, acc2[6]); acc2[7] = ffma2(wd, q3.y, acc2[7]);
            }
            #pragma unroll 4
            for (int j = 0; j < 16; j++) {
                int k = kh*16 + j;
                ull wd = f2dup(w2_s[(128 + k)*32 + col]);
                const float* hp = hlow + k*32;
                ulonglong2 q0 = *(const ulonglong2*)(hp);
                ulonglong2 q1 = *(const ulonglong2*)(hp + 4);
                ulonglong2 q2 = *(const ulonglong2*)(hp + 8);
                ulonglong2 q3 = *(const ulonglong2*)(hp + 12);
                acc2[0] = ffma2(wd, q0.x, acc2[0]); acc2[1] = ffma2(wd, q0.y, acc2[1]);
                acc2[2] = ffma2(wd, q1.x, acc2[2]); acc2[3] = ffma2(wd, q1.y, acc2[3]);
                acc2[4] = ffma2(wd, q2.x, acc2[4]); acc2[5] = ffma2(wd, q2.y, acc2[5]);
                acc2[6] = ffma2(wd, q3.x, acc2[6]); acc2[7] = ffma2(wd, q3.y, acc2[7]);
            }
            if (kh == 0) {
                #pragma unroll
                for (int m = 0; m < 8; m++) acc2[m] = fadd2(acc2[m], f2pack(ax[2*m], ax[2*m+1]));
            }
        }
        __syncthreads();   // update01 reads of z0 done before z2 overwrites it
        if (act2) {
            float* zp = z2_s + kh*(32*33) + col*33 + bg*16;
            #pragma unroll
            for (int m = 0; m < 8; m++) {
                float2 u = f2unpack(acc2[m]);
                zp[2*m] = u.x; zp[2*m + 1] = u.y;
            }
        }
        __syncthreads();
        if (tid < 256 && act2) {
            float zg[4];
            #pragma unroll
            for (int g = 0; g < 4; g++) {
                const float* zr = z2_s + (g*8 + uh)*33 + ub;
                float sum = zr[0];
                #pragma unroll
                for (int q = 1; q < 8; q++) sum += zr[q*(32*33)];
                zg[g] = sum;
            }
            float iv = 1.0f / (1.0f + expf(-zg[0]));
            float fv = 1.0f / (1.0f + expf(-zg[1]));
            float cv = tanhf(zg[2]);
            float ov = 1.0f / (1.0f + expf(-zg[3]));
            cst[2] = fv*cst[2] + iv*cv;
            float hn = ov * tanhf(cst[2]);
            g_h[((2*2 + cp)*128 + htile*8 + uh)*256 + btile*32 + ub] = hn;
        }
        __threadfence();
        group_barrier(btile, &gen);
    }
}

__global__ void out_kernel(const float* __restrict__ rw, const float* __restrict__ rb,
                           float* __restrict__ out) {
    int b = threadIdx.x;
    const int p = (TT + 1) & 1;
    float a0 = rb[0], a1 = rb[1];
    #pragma unroll 4
    for (int h = 0; h < HH; h++) {
        float hv = g_h[((2*2 + p)*128 + h)*256 + b];
        a0 += hv * rw[h*2 + 0];
        a1 += hv * rw[h*2 + 1];
    }
    out[b*2 + 0] = a0;
    out[b*2 + 1] = a1;
}

extern "C" void kernel_launch(void* const* d_in, const int* in_sizes, int n_in,
                              void* d_out, int out_size) {
    (void)in_sizes; (void)n_in; (void)out_size;
    const float* hrrp     = (const float*)d_in[0];
    const float* ampc     = (const float*)d_in[1];
    const float* phc      = (const float*)d_in[2];
    const float* rd       = (const float*)d_in[3];
    const float* f_amp_w  = (const float*)d_in[4];
    const float* f_amp_b  = (const float*)d_in[5];
    const float* f_ph_w   = (const float*)d_in[6];
    const float* f_ph_b   = (const float*)d_in[7];
    const float* f_gate_w = (const float*)d_in[8];
    const float* f_gate_b = (const float*)d_in[9];
    const float* f_rl_w1  = (const float*)d_in[10];
    const float* f_rl_b1  = (const float*)d_in[11];
    const float* f_rl_w2  = (const float*)d_in[12];
    const float* f_rl_b2  = (const float*)d_in[13];
    const float* f_q_w    = (const float*)d_in[14];
    const float* f_q_b    = (const float*)d_in[15];
    const float* f_k_w    = (const float*)d_in[16];
    const float* f_k_b    = (const float*)d_in[17];
    const float* f_v_w    = (const float*)d_in[18];
    const float* f_v_b    = (const float*)d_in[19];
    const float* f_out_w  = (const float*)d_in[20];
    const float* f_out_b  = (const float*)d_in[21];
    const float* base_w0  = (const float*)d_in[22];
    const float* base_b0  = (const float*)d_in[23];
    const float* gam_w0   = (const float*)d_in[24];
    const float* base_w12 = (const float*)d_in[25];
    const float* base_b12 = (const float*)d_in[26];
    const float* gam_w12  = (const float*)d_in[27];
    const float* reg_w    = (const float*)d_in[28];
    const float* reg_b    = (const float*)d_in[29];
    float* out = (float*)d_out;

    float *p_cat, *p_rlh1, *p_corr, *p_rl, *p_q, *p_k, *p_v, *p_av, *p_gamma;
    float *p_A0, *p_A1, *p_A2, *p_Bp0, *p_Bp1, *p_Bp2;
    cudaGetSymbolAddress((void**)&p_cat,   g_cat);
    cudaGetSymbolAddress((void**)&p_rlh1,  g_rlh1);
    cudaGetSymbolAddress((void**)&p_corr,  g_corr);
    cudaGetSymbolAddress((void**)&p_rl,    g_rl);
    cudaGetSymbolAddress((void**)&p_q,     g_q);
    cudaGetSymbolAddress((void**)&p_k,     g_k);
    cudaGetSymbolAddress((void**)&p_v,     g_v);
    cudaGetSymbolAddress((void**)&p_av,    g_av);
    cudaGetSymbolAddress((void**)&p_gamma, g_gamma);
    cudaGetSymbolAddress((void**)&p_A0,    g_A0);
    cudaGetSymbolAddress((void**)&p_A1,    g_A1);
    cudaGetSymbolAddress((void**)&p_A2,    g_A2);
    cudaGetSymbolAddress((void**)&p_Bp0,   g_Bp0);
    cudaGetSymbolAddress((void**)&p_Bp1,   g_Bp1);
    cudaGetSymbolAddress((void**)&p_Bp2,   g_Bp2);

    pack_kernel<<<1168, 256>>>(base_w0, gam_w0, gam_w12);
    ew1_kernel<<<65536, 256>>>(ampc, phc, rd, f_amp_w, f_amp_b, f_ph_w, f_ph_b, f_rl_w1, f_rl_b1);

    dim3 gF(1, 1024), gA(4, 1024);
    gemm_kernel<<<gF, 256>>>(p_cat,  f_gate_w, f_gate_b, p_corr, MROWS, 128, 256, 3, 0, nullptr);
    gemm_kernel<<<gF, 256>>>(p_rlh1, f_rl_w2,  f_rl_b2,  p_rl,   MROWS, 128, 128, 1, 0, nullptr);
    gemm_kernel<<<gF, 256>>>(p_corr, f_q_w,    f_q_b,    p_q,    MROWS, 128, 128, 0, 0, nullptr);
    gemm_kernel<<<gF, 256>>>(p_rl,   f_k_w,    f_k_b,    p_k,    MROWS, 128, 128, 0, 0, nullptr);
    gemm_kernel<<<gF, 256>>>(p_rl,   f_v_w,    f_v_b,    p_v,    MROWS, 128, 128, 0, 0, nullptr);
    ew3_kernel<<<MROWS, 128>>>();
    gemm_kernel<<<gF, 256>>>(p_av,   f_out_w,  f_out_b,  p_gamma, MROWS, 128, 128, 0, 0, nullptr);

    gemm_kernel<<<gA, 256>>>(p_gamma, p_Bp0, base_b0,        p_A0, MROWS, 512, 328, 0, 2, hrrp);
    gemm_kernel<<<gA, 256>>>(p_gamma, p_Bp1, base_b12,       p_A1, MROWS, 512, 128, 0, 1, nullptr);
    gemm_kernel<<<gA, 256>>>(p_gamma, p_Bp2, base_b12 + 512, p_A2, MROWS, 512, 128, 0, 1, nullptr);

    bar_init_kernel<<<1, 256>>>();
    const int SMEM_BYTES = (4096 + 8192 + 8192 + 12288 + 2*8*32*33) * 4;  // 198656
    cudaFuncSetAttribute(lstm_kernel, cudaFuncAttributeMaxDynamicSharedMemorySize, SMEM_BYTES);
    lstm_kernel<<<128, 512, SMEM_BYTES>>>(base_w0, base_w12);
    out_kernel<<<1, 256>>>(reg_w, reg_b, out);
}